// round 12
// baseline (speedup 1.0000x reference)
#include <cuda_runtime.h>
#include <cuda_fp16.h>
#include <math.h>

#define N_NODES 50000
#define N_EDGES 800000

// ---------------- scratch (no cudaMalloc allowed) ----------------
__device__ float  g_q[N_NODES * 128];
__device__ __half g_kvh[N_NODES * 256];  // packed per row: [k(4)|v(4)] x 32 lanes
__device__ float  g_skip[N_NODES * 32];
__device__ int    g_deg[N_NODES];
__device__ int    g_off[N_NODES];       // exclusive prefix; after scatter = inclusive end
__device__ int2   g_csr[N_EDGES];       // (src, bitcast(weight)) grouped by dst
__device__ int    g_bsums[64];

// ================= tf32 tensor-core GEMM (proven R2/R7 style) ==============
#define BM 128
#define BN 128
#define BK 32

__device__ __forceinline__ unsigned f2tf(float x) {
    unsigned r;
    asm("cvt.rna.tf32.f32 %0, %1;" : "=r"(r) : "f"(x));
    return r;
}

__device__ __forceinline__ void mma_tf32(float* c, const unsigned* a,
                                         unsigned b0, unsigned b1) {
    asm volatile(
        "mma.sync.aligned.m16n8k8.row.col.f32.tf32.tf32.f32 "
        "{%0,%1,%2,%3}, {%4,%5,%6,%7}, {%8,%9}, {%0,%1,%2,%3};\n"
        : "+f"(c[0]), "+f"(c[1]), "+f"(c[2]), "+f"(c[3])
        : "r"(a[0]), "r"(a[1]), "r"(a[2]), "r"(a[3]), "r"(b0), "r"(b1));
}

__global__ void __launch_bounds__(256, 2) gemm_tf32(
    const float* __restrict__ x, const float* __restrict__ t,
    const float* __restrict__ Wq, const float* __restrict__ bq,
    const float* __restrict__ Wk, const float* __restrict__ bk,
    const float* __restrict__ Wv, const float* __restrict__ bv,
    const float* __restrict__ Ws, const float* __restrict__ bs,
    int n, int sliceBase)
{
    __shared__ float As[BM][BK + 4];
    __shared__ float Bs[BK][BN + 8];

    const int m0 = blockIdx.x * BM;
    const int slice = blockIdx.y + sliceBase;

    const float* Bmat; const float* bias; float* outp = nullptr;
    int voff = 0; bool packed = false; int bw;
    if (slice == 0)      { Bmat = Wq; bias = bq; outp = g_q;    bw = 128; }
    else if (slice == 1) { Bmat = Wk; bias = bk; packed = true; voff = 0; bw = 128; }
    else if (slice == 2) { Bmat = Wv; bias = bv; packed = true; voff = 4; bw = 128; }
    else                 { Bmat = Ws; bias = bs; outp = g_skip; bw = 32;  }

    const int tid = threadIdx.x;
    const int lane = tid & 31;
    const int wid = tid >> 5;
    const int warp_m = wid & 3;
    const int warp_n = wid >> 2;
    const int g = lane >> 2;
    const int tig = lane & 3;

    float acc[2][8][4];
    #pragma unroll
    for (int mi = 0; mi < 2; mi++)
        #pragma unroll
        for (int ni = 0; ni < 8; ni++)
            #pragma unroll
            for (int c = 0; c < 4; c++) acc[mi][ni][c] = 0.f;

    float4 ar[4];
    float4 br[4];

    const int a_row = tid >> 1;
    const int a_f4  = (tid & 1) * 4;
    const int b_col4 = tid & 31;

    auto loadA = [&](int k0) {
        const int mg = m0 + a_row;
        const int xbase = (k0 < 128 ? k0 : k0 - 128);
        float mult = 0.f;
        if (mg < n) mult = (k0 < 128) ? 1.f : t[mg];
        const float4* xr = (const float4*)&x[(size_t)(mg < n ? mg : 0) * 128 + xbase];
        #pragma unroll
        for (int i = 0; i < 4; i++) {
            float4 v = xr[a_f4 + i];
            ar[i].x = v.x * mult; ar[i].y = v.y * mult;
            ar[i].z = v.z * mult; ar[i].w = v.w * mult;
        }
    };
    auto storeA = [&]() {
        #pragma unroll
        for (int i = 0; i < 4; i++) {
            float4 v;
            v.x = __uint_as_float(f2tf(ar[i].x));
            v.y = __uint_as_float(f2tf(ar[i].y));
            v.z = __uint_as_float(f2tf(ar[i].z));
            v.w = __uint_as_float(f2tf(ar[i].w));
            *(float4*)&As[a_row][(a_f4 + i) * 4] = v;
        }
    };
    auto loadB = [&](int k0) {
        const int jj = b_col4 * 4;
        #pragma unroll
        for (int i = 0; i < 4; i++) {
            const int row = wid + i * 8;
            if (jj < bw) br[i] = *(const float4*)&Bmat[(size_t)(k0 + row) * bw + jj];
            else         br[i] = make_float4(0.f, 0.f, 0.f, 0.f);
        }
    };
    auto storeB = [&]() {
        const int jj = b_col4 * 4;
        #pragma unroll
        for (int i = 0; i < 4; i++) {
            const int row = wid + i * 8;
            float4 v;
            v.x = __uint_as_float(f2tf(br[i].x));
            v.y = __uint_as_float(f2tf(br[i].y));
            v.z = __uint_as_float(f2tf(br[i].z));
            v.w = __uint_as_float(f2tf(br[i].w));
            *(float4*)&Bs[row][jj] = v;
        }
    };

    loadA(0); loadB(0);
    storeA(); storeB();
    __syncthreads();

    for (int k0 = 0; k0 < 256; k0 += BK) {
        const bool has_next = (k0 + BK) < 256;
        if (has_next) { loadA(k0 + BK); loadB(k0 + BK); }

        #pragma unroll
        for (int ks = 0; ks < 4; ks++) {
            const int kk = ks * 8;
            unsigned afrag[2][4];
            #pragma unroll
            for (int mi = 0; mi < 2; mi++) {
                const int r0 = warp_m * 32 + mi * 16 + g;
                afrag[mi][0] = __float_as_uint(As[r0][kk + tig]);
                afrag[mi][1] = __float_as_uint(As[r0 + 8][kk + tig]);
                afrag[mi][2] = __float_as_uint(As[r0][kk + tig + 4]);
                afrag[mi][3] = __float_as_uint(As[r0 + 8][kk + tig + 4]);
            }
            #pragma unroll
            for (int ni = 0; ni < 8; ni++) {
                const int cb = warp_n * 64 + ni * 8 + g;
                const unsigned b0 = __float_as_uint(Bs[kk + tig][cb]);
                const unsigned b1 = __float_as_uint(Bs[kk + tig + 4][cb]);
                mma_tf32(acc[0][ni], afrag[0], b0, b1);
                mma_tf32(acc[1][ni], afrag[1], b0, b1);
            }
        }
        __syncthreads();
        if (has_next) { storeA(); storeB(); __syncthreads(); }
    }

    #pragma unroll
    for (int mi = 0; mi < 2; mi++) {
        const int row = warp_m * 32 + mi * 16 + g;
        #pragma unroll
        for (int ni = 0; ni < 8; ni++) {
            const int col = warp_n * 64 + ni * 8 + 2 * tig;
            if (col >= bw) continue;
            const float bb0 = bias[col];
            const float bb1 = bias[col + 1];
            const int mg0 = m0 + row;
            const int mg1 = m0 + row + 8;
            if (packed) {
                const int hidx = ((col >> 2) << 3) + (col & 3) + voff;
                if (mg0 < n) {
                    __half2 h = __floats2half2_rn(acc[mi][ni][0] + bb0,
                                                  acc[mi][ni][1] + bb1);
                    *(__half2*)&g_kvh[(size_t)mg0 * 256 + hidx] = h;
                }
                if (mg1 < n) {
                    __half2 h = __floats2half2_rn(acc[mi][ni][2] + bb0,
                                                  acc[mi][ni][3] + bb1);
                    *(__half2*)&g_kvh[(size_t)mg1 * 256 + hidx] = h;
                }
            } else {
                if (mg0 < n) {
                    float2 o; o.x = acc[mi][ni][0] + bb0; o.y = acc[mi][ni][1] + bb1;
                    *(float2*)&outp[(size_t)mg0 * bw + col] = o;
                }
                if (mg1 < n) {
                    float2 o; o.x = acc[mi][ni][2] + bb0; o.y = acc[mi][ni][3] + bb1;
                    *(float2*)&outp[(size_t)mg1 * bw + col] = o;
                }
            }
        }
    }
}

// ================= CSR build ===============================================
__global__ void count_deg(const int* __restrict__ ei, int nE) {
    const int e = blockIdx.x * blockDim.x + threadIdx.x;
    if (e < nE) atomicAdd(&g_deg[ei[nE + e]], 1);
}

#define SCAN_B 1024
__global__ void scan1(int n) {
    __shared__ int sh[SCAN_B];
    const int tid = threadIdx.x;
    const int i = blockIdx.x * SCAN_B + tid;
    const int v = (i < n) ? g_deg[i] : 0;
    sh[tid] = v;
    __syncthreads();
    #pragma unroll
    for (int off = 1; off < SCAN_B; off <<= 1) {
        int u = (tid >= off) ? sh[tid - off] : 0;
        __syncthreads();
        sh[tid] += u;
        __syncthreads();
    }
    if (i < n) g_off[i] = sh[tid] - v;   // exclusive
    if (tid == SCAN_B - 1) g_bsums[blockIdx.x] = sh[tid];
}

__global__ void scan2(int nb) {
    __shared__ int sh[64];
    const int tid = threadIdx.x;
    const int v = (tid < nb) ? g_bsums[tid] : 0;
    sh[tid] = v;
    __syncthreads();
    #pragma unroll
    for (int off = 1; off < 64; off <<= 1) {
        int u = (tid >= off) ? sh[tid - off] : 0;
        __syncthreads();
        sh[tid] += u;
        __syncthreads();
    }
    if (tid < nb) g_bsums[tid] = sh[tid] - v;  // exclusive
}

__global__ void scan3(int n) {
    const int i = blockIdx.x * SCAN_B + threadIdx.x;
    if (i < n && blockIdx.x > 0) g_off[i] += g_bsums[blockIdx.x];
}

// bump g_off[dst] directly: after this kernel g_off[dst] = inclusive end.
__global__ void scatter_csr(const int* __restrict__ ei,
                            const float* __restrict__ ew, int nE) {
    const int e = blockIdx.x * blockDim.x + threadIdx.x;
    if (e >= nE) return;
    const int src = ei[e];
    const int dst = ei[nE + e];
    const int pos = atomicAdd(&g_off[dst], 1);
    int2 sw;
    sw.x = src;
    sw.y = __float_as_int(ew[e]);
    g_csr[pos] = sw;
}

// ============ Fused node pass: attention aggregate + epilogue ==============
// One warp per node; packed fp16 kv; 8-deep gather pipeline; edge algebra:
//   alpha = q.k + wt*(q.We) + q.be ;  Sum (v+e)p = Sum v p + We*Sum(wt p) + be*Sum p
__global__ void __launch_bounds__(256) node_kernel(
    const float* __restrict__ x,
    const float* __restrict__ We, const float* __restrict__ be,
    const float* __restrict__ Wmlp, const float* __restrict__ bmlp,
    float* __restrict__ out, int n)
{
    __shared__ float w_sh[32 * 256];
    __shared__ float bm_sh[256];
    for (int i = threadIdx.x; i < 32 * 256; i += 256) w_sh[i] = Wmlp[i];
    if (threadIdx.x < 256) bm_sh[threadIdx.x] = bmlp[threadIdx.x];
    __syncthreads();

    const int warp = threadIdx.x >> 5;
    const int lane = threadIdx.x & 31;
    const int nn = blockIdx.x * 8 + warp;
    if (nn >= n) return;

    const float4 We4 = ((const float4*)We)[lane];
    const float4 be4 = ((const float4*)be)[lane];
    const float4 q4 = ((const float4*)g_q)[nn * 32 + lane];

    // per-head dots q.We and q.be (replicated across the head's 8 lanes)
    float qWe = q4.x * We4.x + q4.y * We4.y + q4.z * We4.z + q4.w * We4.w;
    float qbe = q4.x * be4.x + q4.y * be4.y + q4.z * be4.z + q4.w * be4.w;
    #pragma unroll
    for (int m = 1; m <= 4; m <<= 1) {
        qWe += __shfl_xor_sync(0xffffffffu, qWe, m);
        qbe += __shfl_xor_sync(0xffffffffu, qbe, m);
    }

    const int cnt = g_deg[nn];
    const int end = g_off[nn];          // inclusive end (scatter bumped it)
    const int beg = end - cnt;

    float4 macc = make_float4(0.f, 0.f, 0.f, 0.f);
    float dsum = 0.f;   // Sum p
    float wsum = 0.f;   // Sum wt*p

    const uint4* kvp = (const uint4*)g_kvh;

    int j = beg;
    const int lim8 = beg + (cnt & ~7);
    for (; j < lim8; j += 8) {
        int2 sw[8];
        #pragma unroll
        for (int i = 0; i < 8; i++) sw[i] = g_csr[j + i];
        uint4 raw[8];
        #pragma unroll
        for (int i = 0; i < 8; i++) raw[i] = kvp[sw[i].x * 32 + lane];

        float s[8];
        #pragma unroll
        for (int i = 0; i < 8; i++) {
            const float2 k01 = __half22float2(*(const __half2*)&raw[i].x);
            const float2 k23 = __half22float2(*(const __half2*)&raw[i].y);
            s[i] = q4.x * k01.x + q4.y * k01.y + q4.z * k23.x + q4.w * k23.y;
        }
        #pragma unroll
        for (int i = 0; i < 8; i++) {
            s[i] += __shfl_xor_sync(0xffffffffu, s[i], 1);
            s[i] += __shfl_xor_sync(0xffffffffu, s[i], 2);
            s[i] += __shfl_xor_sync(0xffffffffu, s[i], 4);
        }
        #pragma unroll
        for (int i = 0; i < 8; i++) {
            const float2 v01 = __half22float2(*(const __half2*)&raw[i].z);
            const float2 v23 = __half22float2(*(const __half2*)&raw[i].w);
            const float wt = __int_as_float(sw[i].y);
            const float alpha = s[i] + fmaf(wt, qWe, qbe);
            const float p = __expf(alpha * 0.17677669529663689f);  // 1/sqrt(32)
            dsum += p;
            wsum = fmaf(wt, p, wsum);
            macc.x = fmaf(v01.x, p, macc.x);
            macc.y = fmaf(v01.y, p, macc.y);
            macc.z = fmaf(v23.x, p, macc.z);
            macc.w = fmaf(v23.y, p, macc.w);
        }
    }
    const int lim4 = beg + (cnt & ~3);
    for (; j < lim4; j += 4) {
        int2 sw[4];
        #pragma unroll
        for (int i = 0; i < 4; i++) sw[i] = g_csr[j + i];
        uint4 raw[4];
        #pragma unroll
        for (int i = 0; i < 4; i++) raw[i] = kvp[sw[i].x * 32 + lane];
        float s[4];
        #pragma unroll
        for (int i = 0; i < 4; i++) {
            const float2 k01 = __half22float2(*(const __half2*)&raw[i].x);
            const float2 k23 = __half22float2(*(const __half2*)&raw[i].y);
            s[i] = q4.x * k01.x + q4.y * k01.y + q4.z * k23.x + q4.w * k23.y;
        }
        #pragma unroll
        for (int i = 0; i < 4; i++) {
            s[i] += __shfl_xor_sync(0xffffffffu, s[i], 1);
            s[i] += __shfl_xor_sync(0xffffffffu, s[i], 2);
            s[i] += __shfl_xor_sync(0xffffffffu, s[i], 4);
        }
        #pragma unroll
        for (int i = 0; i < 4; i++) {
            const float2 v01 = __half22float2(*(const __half2*)&raw[i].z);
            const float2 v23 = __half22float2(*(const __half2*)&raw[i].w);
            const float wt = __int_as_float(sw[i].y);
            const float alpha = s[i] + fmaf(wt, qWe, qbe);
            const float p = __expf(alpha * 0.17677669529663689f);
            dsum += p;
            wsum = fmaf(wt, p, wsum);
            macc.x = fmaf(v01.x, p, macc.x);
            macc.y = fmaf(v01.y, p, macc.y);
            macc.z = fmaf(v23.x, p, macc.z);
            macc.w = fmaf(v23.y, p, macc.w);
        }
    }
    for (; j < end; j++) {
        const int2 sw = g_csr[j];
        const uint4 raw = kvp[sw.x * 32 + lane];
        const float2 k01 = __half22float2(*(const __half2*)&raw.x);
        const float2 k23 = __half22float2(*(const __half2*)&raw.y);
        const float2 v01 = __half22float2(*(const __half2*)&raw.z);
        const float2 v23 = __half22float2(*(const __half2*)&raw.w);
        float s = q4.x * k01.x + q4.y * k01.y + q4.z * k23.x + q4.w * k23.y;
        s += __shfl_xor_sync(0xffffffffu, s, 1);
        s += __shfl_xor_sync(0xffffffffu, s, 2);
        s += __shfl_xor_sync(0xffffffffu, s, 4);
        const float wt = __int_as_float(sw.y);
        const float alpha = s + fmaf(wt, qWe, qbe);
        const float p = __expf(alpha * 0.17677669529663689f);
        dsum += p;
        wsum = fmaf(wt, p, wsum);
        macc.x = fmaf(v01.x, p, macc.x);
        macc.y = fmaf(v01.y, p, macc.y);
        macc.z = fmaf(v23.x, p, macc.z);
        macc.w = fmaf(v23.y, p, macc.w);
    }

    const float inv = 1.f / (dsum + 1e-16f);
    float4 z4;
    z4.x = (macc.x + We4.x * wsum + be4.x * dsum) * inv;
    z4.y = (macc.y + We4.y * wsum + be4.y * dsum) * inv;
    z4.z = (macc.z + We4.z * wsum + be4.z * dsum) * inv;
    z4.w = (macc.w + We4.w * wsum + be4.w * dsum) * inv;

    #pragma unroll
    for (int m = 8; m <= 16; m <<= 1) {
        z4.x += __shfl_xor_sync(0xffffffffu, z4.x, m);
        z4.y += __shfl_xor_sync(0xffffffffu, z4.y, m);
        z4.z += __shfl_xor_sync(0xffffffffu, z4.z, m);
        z4.w += __shfl_xor_sync(0xffffffffu, z4.w, m);
    }

    const int u = lane & 7;
    const float4 sk = ((const float4*)g_skip)[nn * 8 + u];
    float4 y4;
    y4.x = tanhf(z4.x * 0.25f + sk.x);
    y4.y = tanhf(z4.y * 0.25f + sk.y);
    y4.z = tanhf(z4.z * 0.25f + sk.z);
    y4.w = tanhf(z4.w * 0.25f + sk.w);

    float accS[4] = {0.f, 0.f, 0.f, 0.f};
    float accH[4] = {0.f, 0.f, 0.f, 0.f};
    #pragma unroll
    for (int uu = 0; uu < 8; uu++) {
        const float b0 = __shfl_sync(0xffffffffu, y4.x, uu);
        const float b1 = __shfl_sync(0xffffffffu, y4.y, uu);
        const float b2 = __shfl_sync(0xffffffffu, y4.z, uu);
        const float b3 = __shfl_sync(0xffffffffu, y4.w, uu);
        const int d0 = 4 * uu;
        #pragma unroll
        for (int k = 0; k < 4; k++) {
            const int c = lane + 32 * k;
            accS[k] = fmaf(b0, w_sh[(d0 + 0) * 256 + c], accS[k]);
            accS[k] = fmaf(b1, w_sh[(d0 + 1) * 256 + c], accS[k]);
            accS[k] = fmaf(b2, w_sh[(d0 + 2) * 256 + c], accS[k]);
            accS[k] = fmaf(b3, w_sh[(d0 + 3) * 256 + c], accS[k]);
            accH[k] = fmaf(b0, w_sh[(d0 + 0) * 256 + 128 + c], accH[k]);
            accH[k] = fmaf(b1, w_sh[(d0 + 1) * 256 + 128 + c], accH[k]);
            accH[k] = fmaf(b2, w_sh[(d0 + 2) * 256 + 128 + c], accH[k]);
            accH[k] = fmaf(b3, w_sh[(d0 + 3) * 256 + 128 + c], accH[k]);
        }
    }
    #pragma unroll
    for (int k = 0; k < 4; k++) {
        const int c = lane + 32 * k;
        const float sc = tanhf(accS[k] + bm_sh[c]);
        const float sh = tanhf(accH[k] + bm_sh[128 + c]);
        out[(size_t)nn * 128 + c] = fmaf(x[(size_t)nn * 128 + c], sc, sh);
    }
}

// ================= launch ==================================================
extern "C" void kernel_launch(void* const* d_in, const int* in_sizes, int n_in,
                              void* d_out, int out_size)
{
    const float* x     = (const float*)d_in[0];
    const float* t     = (const float*)d_in[1];
    const int*   ei    = (const int*)  d_in[2];
    const float* ew    = (const float*)d_in[3];
    const float* Wq    = (const float*)d_in[4];
    const float* bq    = (const float*)d_in[5];
    const float* Wk    = (const float*)d_in[6];
    const float* bk    = (const float*)d_in[7];
    const float* Wv    = (const float*)d_in[8];
    const float* bv    = (const float*)d_in[9];
    const float* We    = (const float*)d_in[10];
    const float* be    = (const float*)d_in[11];
    const float* Wskip = (const float*)d_in[12];
    const float* bskip = (const float*)d_in[13];
    const float* Wmlp  = (const float*)d_in[14];
    const float* bmlp  = (const float*)d_in[15];
    float* out = (float*)d_out;

    const int n  = in_sizes[0] / 128;
    const int nE = in_sizes[3];

    // one-time side stream + fork/join events (same work every call)
    static cudaStream_t sB = nullptr;
    static cudaEvent_t evFork = nullptr, evJoin = nullptr;
    if (sB == nullptr) {
        cudaStreamCreateWithFlags(&sB, cudaStreamNonBlocking);
        cudaEventCreateWithFlags(&evFork, cudaEventDisableTiming);
        cudaEventCreateWithFlags(&evJoin, cudaEventDisableTiming);
    }

    void *degPtr = nullptr;
    cudaGetSymbolAddress(&degPtr, g_deg);

    const int gm = (n + BM - 1) / BM;

    // ---- fork: CSR build + skip GEMM on side stream ----------------------
    cudaEventRecord(evFork, 0);
    cudaStreamWaitEvent(sB, evFork, 0);

    cudaMemsetAsync(degPtr, 0, (size_t)n * sizeof(int), sB);
    count_deg<<<(nE + 255) / 256, 256, 0, sB>>>(ei, nE);
    const int nb = (n + SCAN_B - 1) / SCAN_B;
    scan1<<<nb, SCAN_B, 0, sB>>>(n);
    scan2<<<1, 64, 0, sB>>>(nb);
    scan3<<<nb, SCAN_B, 0, sB>>>(n);
    scatter_csr<<<(nE + 255) / 256, 256, 0, sB>>>(ei, ew, nE);
    gemm_tf32<<<dim3(gm, 1), 256, 0, sB>>>(x, t, Wq, bq, Wk, bk, Wv, bv,
                                           Wskip, bskip, n, 3);  // skip slice
    cudaEventRecord(evJoin, sB);

    // ---- main stream: q,k,v GEMM -----------------------------------------
    gemm_tf32<<<dim3(gm, 3), 256>>>(x, t, Wq, bq, Wk, bk, Wv, bv,
                                    Wskip, bskip, n, 0);

    // ---- join, then fused attention + epilogue ---------------------------
    cudaStreamWaitEvent(0, evJoin, 0);
    node_kernel<<<(n + 7) / 8, 256>>>(x, We, be, Wmlp, bmlp, out, n);
}

// round 13
// speedup vs baseline: 1.1025x; 1.1025x over previous
#include <cuda_runtime.h>
#include <cuda_fp16.h>
#include <math.h>

#define N_NODES 50000
#define N_EDGES 800000

// ---------------- scratch (no cudaMalloc allowed) ----------------
__device__ float  g_q[N_NODES * 128];
__device__ __half g_kvh[N_NODES * 256];  // packed per row: [k(4)|v(4)] x 32 lanes
__device__ float  g_skip[N_NODES * 32];
__device__ int    g_deg[N_NODES];
__device__ int    g_off[N_NODES];       // exclusive prefix; after scatter = inclusive end
__device__ int2   g_csr[N_EDGES];       // (src, bitcast(weight)) grouped by dst
__device__ int    g_bsums[64];

// ================= tf32 tensor-core GEMM (proven R2/R7 style) ==============
#define BM 128
#define BN 128
#define BK 32

__device__ __forceinline__ unsigned f2tf(float x) {
    unsigned r;
    asm("cvt.rna.tf32.f32 %0, %1;" : "=r"(r) : "f"(x));
    return r;
}

__device__ __forceinline__ void mma_tf32(float* c, const unsigned* a,
                                         unsigned b0, unsigned b1) {
    asm volatile(
        "mma.sync.aligned.m16n8k8.row.col.f32.tf32.tf32.f32 "
        "{%0,%1,%2,%3}, {%4,%5,%6,%7}, {%8,%9}, {%0,%1,%2,%3};\n"
        : "+f"(c[0]), "+f"(c[1]), "+f"(c[2]), "+f"(c[3])
        : "r"(a[0]), "r"(a[1]), "r"(a[2]), "r"(a[3]), "r"(b0), "r"(b1));
}

// BW=128: slices 0..2 (q, kv-packed). BW=32: skip slice, only warp_n==0,
// NI=4 ni-tiles (cols 0..31) — 1/4 of the MMA work per CTA.
template<int BW>
__global__ void __launch_bounds__(256, 2) gemm_tf32(
    const float* __restrict__ x, const float* __restrict__ t,
    const float* __restrict__ Wq, const float* __restrict__ bq,
    const float* __restrict__ Wk, const float* __restrict__ bk,
    const float* __restrict__ Wv, const float* __restrict__ bv,
    const float* __restrict__ Ws, const float* __restrict__ bs,
    int n)
{
    __shared__ float As[BM][BK + 4];
    __shared__ float Bs[BK][BN + 8];

    const int m0 = blockIdx.x * BM;
    const int slice = blockIdx.y;

    const float* Bmat; const float* bias; float* outp = nullptr;
    int voff = 0; bool packed = false;
    if (BW == 32) { Bmat = Ws; bias = bs; outp = g_skip; }
    else if (slice == 0)  { Bmat = Wq; bias = bq; outp = g_q; }
    else if (slice == 1)  { Bmat = Wk; bias = bk; packed = true; voff = 0; }
    else                  { Bmat = Wv; bias = bv; packed = true; voff = 4; }

    const int tid = threadIdx.x;
    const int lane = tid & 31;
    const int wid = tid >> 5;
    const int warp_m = wid & 3;
    const int warp_n = wid >> 2;
    const int g = lane >> 2;
    const int tig = lane & 3;

    constexpr int NI = (BW == 128) ? 8 : 4;
    float acc[2][NI][4];
    #pragma unroll
    for (int mi = 0; mi < 2; mi++)
        #pragma unroll
        for (int ni = 0; ni < NI; ni++)
            #pragma unroll
            for (int c = 0; c < 4; c++) acc[mi][ni][c] = 0.f;

    float4 ar[4];
    float4 br[4];

    const int a_row = tid >> 1;
    const int a_f4  = (tid & 1) * 4;
    const int b_col4 = tid & 31;

    auto loadA = [&](int k0) {
        const int mg = m0 + a_row;
        const int xbase = (k0 < 128 ? k0 : k0 - 128);
        float mult = 0.f;
        if (mg < n) mult = (k0 < 128) ? 1.f : t[mg];
        const float4* xr = (const float4*)&x[(size_t)(mg < n ? mg : 0) * 128 + xbase];
        #pragma unroll
        for (int i = 0; i < 4; i++) {
            float4 v = xr[a_f4 + i];
            ar[i].x = v.x * mult; ar[i].y = v.y * mult;
            ar[i].z = v.z * mult; ar[i].w = v.w * mult;
        }
    };
    auto storeA = [&]() {
        #pragma unroll
        for (int i = 0; i < 4; i++) {
            float4 v;
            v.x = __uint_as_float(f2tf(ar[i].x));
            v.y = __uint_as_float(f2tf(ar[i].y));
            v.z = __uint_as_float(f2tf(ar[i].z));
            v.w = __uint_as_float(f2tf(ar[i].w));
            *(float4*)&As[a_row][(a_f4 + i) * 4] = v;
        }
    };
    auto loadB = [&](int k0) {
        const int jj = b_col4 * 4;
        #pragma unroll
        for (int i = 0; i < 4; i++) {
            const int row = wid + i * 8;
            if (jj < BW) br[i] = *(const float4*)&Bmat[(size_t)(k0 + row) * BW + jj];
            else         br[i] = make_float4(0.f, 0.f, 0.f, 0.f);
        }
    };
    auto storeB = [&]() {
        const int jj = b_col4 * 4;
        #pragma unroll
        for (int i = 0; i < 4; i++) {
            const int row = wid + i * 8;
            float4 v;
            v.x = __uint_as_float(f2tf(br[i].x));
            v.y = __uint_as_float(f2tf(br[i].y));
            v.z = __uint_as_float(f2tf(br[i].z));
            v.w = __uint_as_float(f2tf(br[i].w));
            *(float4*)&Bs[row][jj] = v;
        }
    };

    loadA(0); loadB(0);
    storeA(); storeB();
    __syncthreads();

    for (int k0 = 0; k0 < 256; k0 += BK) {
        const bool has_next = (k0 + BK) < 256;
        if (has_next) { loadA(k0 + BK); loadB(k0 + BK); }

        if (BW == 128 || warp_n == 0) {
            #pragma unroll
            for (int ks = 0; ks < 4; ks++) {
                const int kk = ks * 8;
                unsigned afrag[2][4];
                #pragma unroll
                for (int mi = 0; mi < 2; mi++) {
                    const int r0 = warp_m * 32 + mi * 16 + g;
                    afrag[mi][0] = __float_as_uint(As[r0][kk + tig]);
                    afrag[mi][1] = __float_as_uint(As[r0 + 8][kk + tig]);
                    afrag[mi][2] = __float_as_uint(As[r0][kk + tig + 4]);
                    afrag[mi][3] = __float_as_uint(As[r0 + 8][kk + tig + 4]);
                }
                #pragma unroll
                for (int ni = 0; ni < NI; ni++) {
                    const int cb = warp_n * 64 + ni * 8 + g;
                    const unsigned b0 = __float_as_uint(Bs[kk + tig][cb]);
                    const unsigned b1 = __float_as_uint(Bs[kk + tig + 4][cb]);
                    mma_tf32(acc[0][ni], afrag[0], b0, b1);
                    mma_tf32(acc[1][ni], afrag[1], b0, b1);
                }
            }
        }
        __syncthreads();
        if (has_next) { storeA(); storeB(); __syncthreads(); }
    }

    if (BW == 32 && warp_n != 0) return;

    #pragma unroll
    for (int mi = 0; mi < 2; mi++) {
        const int row = warp_m * 32 + mi * 16 + g;
        #pragma unroll
        for (int ni = 0; ni < NI; ni++) {
            const int col = warp_n * 64 + ni * 8 + 2 * tig;
            if (col >= BW) continue;
            const float bb0 = bias[col];
            const float bb1 = bias[col + 1];
            const int mg0 = m0 + row;
            const int mg1 = m0 + row + 8;
            if (packed) {
                const int hidx = ((col >> 2) << 3) + (col & 3) + voff;
                if (mg0 < n) {
                    __half2 h = __floats2half2_rn(acc[mi][ni][0] + bb0,
                                                  acc[mi][ni][1] + bb1);
                    *(__half2*)&g_kvh[(size_t)mg0 * 256 + hidx] = h;
                }
                if (mg1 < n) {
                    __half2 h = __floats2half2_rn(acc[mi][ni][2] + bb0,
                                                  acc[mi][ni][3] + bb1);
                    *(__half2*)&g_kvh[(size_t)mg1 * 256 + hidx] = h;
                }
            } else {
                if (mg0 < n) {
                    float2 o; o.x = acc[mi][ni][0] + bb0; o.y = acc[mi][ni][1] + bb1;
                    *(float2*)&outp[(size_t)mg0 * BW + col] = o;
                }
                if (mg1 < n) {
                    float2 o; o.x = acc[mi][ni][2] + bb0; o.y = acc[mi][ni][3] + bb1;
                    *(float2*)&outp[(size_t)mg1 * BW + col] = o;
                }
            }
        }
    }
}

// ================= CSR build ===============================================
__global__ void count_deg(const int* __restrict__ ei, int nE) {
    const int e = blockIdx.x * blockDim.x + threadIdx.x;
    if (e < nE) atomicAdd(&g_deg[ei[nE + e]], 1);
}

#define SCAN_B 1024
__global__ void scan1(int n) {
    __shared__ int sh[SCAN_B];
    const int tid = threadIdx.x;
    const int i = blockIdx.x * SCAN_B + tid;
    const int v = (i < n) ? g_deg[i] : 0;
    sh[tid] = v;
    __syncthreads();
    #pragma unroll
    for (int off = 1; off < SCAN_B; off <<= 1) {
        int u = (tid >= off) ? sh[tid - off] : 0;
        __syncthreads();
        sh[tid] += u;
        __syncthreads();
    }
    if (i < n) g_off[i] = sh[tid] - v;   // exclusive
    if (tid == SCAN_B - 1) g_bsums[blockIdx.x] = sh[tid];
}

__global__ void scan2(int nb) {
    __shared__ int sh[64];
    const int tid = threadIdx.x;
    const int v = (tid < nb) ? g_bsums[tid] : 0;
    sh[tid] = v;
    __syncthreads();
    #pragma unroll
    for (int off = 1; off < 64; off <<= 1) {
        int u = (tid >= off) ? sh[tid - off] : 0;
        __syncthreads();
        sh[tid] += u;
        __syncthreads();
    }
    if (tid < nb) g_bsums[tid] = sh[tid] - v;  // exclusive
}

__global__ void scan3(int n) {
    const int i = blockIdx.x * SCAN_B + threadIdx.x;
    if (i < n && blockIdx.x > 0) g_off[i] += g_bsums[blockIdx.x];
}

// bump g_off[dst] directly: after this kernel g_off[dst] = inclusive end.
__global__ void scatter_csr(const int* __restrict__ ei,
                            const float* __restrict__ ew, int nE) {
    const int e = blockIdx.x * blockDim.x + threadIdx.x;
    if (e >= nE) return;
    const int src = ei[e];
    const int dst = ei[nE + e];
    const int pos = atomicAdd(&g_off[dst], 1);
    int2 sw;
    sw.x = src;
    sw.y = __float_as_int(ew[e]);
    g_csr[pos] = sw;
}

// ============ Fused node pass: attention aggregate + epilogue ==============
// One warp per node; packed fp16 kv (1 LDG.128/lane/edge); edge-term algebra:
//   alpha = q.k + wt*(q.We) + q.be ;  Sum (v+e)p = Sum v p + We*Sum(wt p) + be*Sum p
__global__ void __launch_bounds__(256) node_kernel(
    const float* __restrict__ x,
    const float* __restrict__ We, const float* __restrict__ be,
    const float* __restrict__ Wmlp, const float* __restrict__ bmlp,
    float* __restrict__ out, int n)
{
    __shared__ float w_sh[32 * 256];
    __shared__ float bm_sh[256];
    for (int i = threadIdx.x; i < 32 * 256; i += 256) w_sh[i] = Wmlp[i];
    if (threadIdx.x < 256) bm_sh[threadIdx.x] = bmlp[threadIdx.x];
    __syncthreads();

    const int warp = threadIdx.x >> 5;
    const int lane = threadIdx.x & 31;
    const int nn = blockIdx.x * 8 + warp;
    if (nn >= n) return;

    const float4 We4 = ((const float4*)We)[lane];
    const float4 be4 = ((const float4*)be)[lane];
    const float4 q4 = ((const float4*)g_q)[nn * 32 + lane];

    // per-head dots q.We and q.be (replicated across the head's 8 lanes)
    float qWe = q4.x * We4.x + q4.y * We4.y + q4.z * We4.z + q4.w * We4.w;
    float qbe = q4.x * be4.x + q4.y * be4.y + q4.z * be4.z + q4.w * be4.w;
    #pragma unroll
    for (int m = 1; m <= 4; m <<= 1) {
        qWe += __shfl_xor_sync(0xffffffffu, qWe, m);
        qbe += __shfl_xor_sync(0xffffffffu, qbe, m);
    }

    const int cnt = g_deg[nn];
    const int end = g_off[nn];          // inclusive end (scatter bumped it)
    const int beg = end - cnt;

    float4 macc = make_float4(0.f, 0.f, 0.f, 0.f);
    float dsum = 0.f;   // Sum p
    float wsum = 0.f;   // Sum wt*p

    const uint4* kvp = (const uint4*)g_kvh;

    int j = beg;
    const int lim = beg + (cnt & ~3);
    for (; j < lim; j += 4) {
        int2 sw[4];
        #pragma unroll
        for (int i = 0; i < 4; i++) sw[i] = g_csr[j + i];
        uint4 raw[4];
        #pragma unroll
        for (int i = 0; i < 4; i++) raw[i] = kvp[sw[i].x * 32 + lane];

        float s[4];
        #pragma unroll
        for (int i = 0; i < 4; i++) {
            const float2 k01 = __half22float2(*(const __half2*)&raw[i].x);
            const float2 k23 = __half22float2(*(const __half2*)&raw[i].y);
            s[i] = q4.x * k01.x + q4.y * k01.y + q4.z * k23.x + q4.w * k23.y;
        }
        #pragma unroll
        for (int i = 0; i < 4; i++) {
            s[i] += __shfl_xor_sync(0xffffffffu, s[i], 1);
            s[i] += __shfl_xor_sync(0xffffffffu, s[i], 2);
            s[i] += __shfl_xor_sync(0xffffffffu, s[i], 4);
        }
        #pragma unroll
        for (int i = 0; i < 4; i++) {
            const float2 v01 = __half22float2(*(const __half2*)&raw[i].z);
            const float2 v23 = __half22float2(*(const __half2*)&raw[i].w);
            const float wt = __int_as_float(sw[i].y);
            const float alpha = s[i] + fmaf(wt, qWe, qbe);
            const float p = __expf(alpha * 0.17677669529663689f);  // 1/sqrt(32)
            dsum += p;
            wsum = fmaf(wt, p, wsum);
            macc.x = fmaf(v01.x, p, macc.x);
            macc.y = fmaf(v01.y, p, macc.y);
            macc.z = fmaf(v23.x, p, macc.z);
            macc.w = fmaf(v23.y, p, macc.w);
        }
    }
    for (; j < end; j++) {
        const int2 sw = g_csr[j];
        const uint4 raw = kvp[sw.x * 32 + lane];
        const float2 k01 = __half22float2(*(const __half2*)&raw.x);
        const float2 k23 = __half22float2(*(const __half2*)&raw.y);
        const float2 v01 = __half22float2(*(const __half2*)&raw.z);
        const float2 v23 = __half22float2(*(const __half2*)&raw.w);
        float s = q4.x * k01.x + q4.y * k01.y + q4.z * k23.x + q4.w * k23.y;
        s += __shfl_xor_sync(0xffffffffu, s, 1);
        s += __shfl_xor_sync(0xffffffffu, s, 2);
        s += __shfl_xor_sync(0xffffffffu, s, 4);
        const float wt = __int_as_float(sw.y);
        const float alpha = s + fmaf(wt, qWe, qbe);
        const float p = __expf(alpha * 0.17677669529663689f);
        dsum += p;
        wsum = fmaf(wt, p, wsum);
        macc.x = fmaf(v01.x, p, macc.x);
        macc.y = fmaf(v01.y, p, macc.y);
        macc.z = fmaf(v23.x, p, macc.z);
        macc.w = fmaf(v23.y, p, macc.w);
    }

    // z = (Sum v p + We*Sum(wt p) + be*Sum p) / (Sum p + eps), per head
    const float inv = 1.f / (dsum + 1e-16f);
    float4 z4;
    z4.x = (macc.x + We4.x * wsum + be4.x * dsum) * inv;
    z4.y = (macc.y + We4.y * wsum + be4.y * dsum) * inv;
    z4.z = (macc.z + We4.z * wsum + be4.z * dsum) * inv;
    z4.w = (macc.w + We4.w * wsum + be4.w * dsum) * inv;

    #pragma unroll
    for (int m = 8; m <= 16; m <<= 1) {
        z4.x += __shfl_xor_sync(0xffffffffu, z4.x, m);
        z4.y += __shfl_xor_sync(0xffffffffu, z4.y, m);
        z4.z += __shfl_xor_sync(0xffffffffu, z4.z, m);
        z4.w += __shfl_xor_sync(0xffffffffu, z4.w, m);
    }

    const int u = lane & 7;
    const float4 sk = ((const float4*)g_skip)[nn * 8 + u];
    float4 y4;
    y4.x = tanhf(z4.x * 0.25f + sk.x);
    y4.y = tanhf(z4.y * 0.25f + sk.y);
    y4.z = tanhf(z4.z * 0.25f + sk.z);
    y4.w = tanhf(z4.w * 0.25f + sk.w);

    float accS[4] = {0.f, 0.f, 0.f, 0.f};
    float accH[4] = {0.f, 0.f, 0.f, 0.f};
    #pragma unroll
    for (int uu = 0; uu < 8; uu++) {
        const float b0 = __shfl_sync(0xffffffffu, y4.x, uu);
        const float b1 = __shfl_sync(0xffffffffu, y4.y, uu);
        const float b2 = __shfl_sync(0xffffffffu, y4.z, uu);
        const float b3 = __shfl_sync(0xffffffffu, y4.w, uu);
        const int d0 = 4 * uu;
        #pragma unroll
        for (int k = 0; k < 4; k++) {
            const int c = lane + 32 * k;
            accS[k] = fmaf(b0, w_sh[(d0 + 0) * 256 + c], accS[k]);
            accS[k] = fmaf(b1, w_sh[(d0 + 1) * 256 + c], accS[k]);
            accS[k] = fmaf(b2, w_sh[(d0 + 2) * 256 + c], accS[k]);
            accS[k] = fmaf(b3, w_sh[(d0 + 3) * 256 + c], accS[k]);
            accH[k] = fmaf(b0, w_sh[(d0 + 0) * 256 + 128 + c], accH[k]);
            accH[k] = fmaf(b1, w_sh[(d0 + 1) * 256 + 128 + c], accH[k]);
            accH[k] = fmaf(b2, w_sh[(d0 + 2) * 256 + 128 + c], accH[k]);
            accH[k] = fmaf(b3, w_sh[(d0 + 3) * 256 + 128 + c], accH[k]);
        }
    }
    #pragma unroll
    for (int k = 0; k < 4; k++) {
        const int c = lane + 32 * k;
        const float sc = tanhf(accS[k] + bm_sh[c]);
        const float sh = tanhf(accH[k] + bm_sh[128 + c]);
        out[(size_t)nn * 128 + c] = fmaf(x[(size_t)nn * 128 + c], sc, sh);
    }
}

// ================= launch ==================================================
extern "C" void kernel_launch(void* const* d_in, const int* in_sizes, int n_in,
                              void* d_out, int out_size)
{
    const float* x     = (const float*)d_in[0];
    const float* t     = (const float*)d_in[1];
    const int*   ei    = (const int*)  d_in[2];
    const float* ew    = (const float*)d_in[3];
    const float* Wq    = (const float*)d_in[4];
    const float* bq    = (const float*)d_in[5];
    const float* Wk    = (const float*)d_in[6];
    const float* bk    = (const float*)d_in[7];
    const float* Wv    = (const float*)d_in[8];
    const float* bv    = (const float*)d_in[9];
    const float* We    = (const float*)d_in[10];
    const float* be    = (const float*)d_in[11];
    const float* Wskip = (const float*)d_in[12];
    const float* bskip = (const float*)d_in[13];
    const float* Wmlp  = (const float*)d_in[14];
    const float* bmlp  = (const float*)d_in[15];
    float* out = (float*)d_out;

    const int n  = in_sizes[0] / 128;
    const int nE = in_sizes[3];

    // one-time side stream + fork/join events (same work every call)
    static cudaStream_t sB = nullptr;
    static cudaEvent_t evFork = nullptr, evJoin = nullptr;
    if (sB == nullptr) {
        cudaStreamCreateWithFlags(&sB, cudaStreamNonBlocking);
        cudaEventCreateWithFlags(&evFork, cudaEventDisableTiming);
        cudaEventCreateWithFlags(&evJoin, cudaEventDisableTiming);
    }

    void *degPtr = nullptr;
    cudaGetSymbolAddress(&degPtr, g_deg);

    // ---- fork: CSR build on side stream, GEMM on main stream -------------
    cudaEventRecord(evFork, 0);
    cudaStreamWaitEvent(sB, evFork, 0);

    cudaMemsetAsync(degPtr, 0, (size_t)n * sizeof(int), sB);
    count_deg<<<(nE + 255) / 256, 256, 0, sB>>>(ei, nE);
    const int nb = (n + SCAN_B - 1) / SCAN_B;
    scan1<<<nb, SCAN_B, 0, sB>>>(n);
    scan2<<<1, 64, 0, sB>>>(nb);
    scan3<<<nb, SCAN_B, 0, sB>>>(n);
    scatter_csr<<<(nE + 255) / 256, 256, 0, sB>>>(ei, ew, nE);
    cudaEventRecord(evJoin, sB);

    // main stream: q,k,v (BW=128, 3 slices) then cheap skip slice (BW=32)
    const int gm = (n + BM - 1) / BM;
    gemm_tf32<128><<<dim3(gm, 3), 256>>>(x, t, Wq, bq, Wk, bk, Wv, bv,
                                         Wskip, bskip, n);
    gemm_tf32<32><<<dim3(gm, 1), 256>>>(x, t, Wq, bq, Wk, bk, Wv, bv,
                                        Wskip, bskip, n);

    // ---- join, then fused attention + epilogue ---------------------------
    cudaStreamWaitEvent(0, evJoin, 0);
    node_kernel<<<(n + 7) / 8, 256>>>(x, We, be, Wmlp, bmlp, out, n);
}

// round 14
// speedup vs baseline: 1.1612x; 1.0533x over previous
#include <cuda_runtime.h>
#include <cuda_fp16.h>
#include <math.h>

#define N_NODES 50000
#define N_EDGES 800000

// ---------------- scratch (no cudaMalloc allowed) ----------------
__device__ float  g_q[N_NODES * 128];
__device__ __half g_kvh[N_NODES * 256];  // packed per row: [k(4)|v(4)] x 32 lanes
__device__ float  g_skip[N_NODES * 32];
__device__ int    g_deg[N_NODES];
__device__ int    g_off[N_NODES];       // exclusive prefix; after scatter = inclusive end
__device__ int2   g_csr[N_EDGES];       // (src, bitcast(weight)) grouped by dst
__device__ int    g_bsums[64];
__device__ int    g_work;               // work-stealing cursor for node pass

// ================= tf32 tensor-core GEMM (proven R2/R7 style) ==============
#define BM 128
#define BN 128
#define BK 32

__device__ __forceinline__ unsigned f2tf(float x) {
    unsigned r;
    asm("cvt.rna.tf32.f32 %0, %1;" : "=r"(r) : "f"(x));
    return r;
}

__device__ __forceinline__ void mma_tf32(float* c, const unsigned* a,
                                         unsigned b0, unsigned b1) {
    asm volatile(
        "mma.sync.aligned.m16n8k8.row.col.f32.tf32.tf32.f32 "
        "{%0,%1,%2,%3}, {%4,%5,%6,%7}, {%8,%9}, {%0,%1,%2,%3};\n"
        : "+f"(c[0]), "+f"(c[1]), "+f"(c[2]), "+f"(c[3])
        : "r"(a[0]), "r"(a[1]), "r"(a[2]), "r"(a[3]), "r"(b0), "r"(b1));
}

// BW=128: slices 0..2 (q, kv-packed). BW=32: skip slice, only warp_n==0,
// NI=4 ni-tiles (cols 0..31) — 1/4 of the MMA work per CTA.
template<int BW>
__global__ void __launch_bounds__(256, 2) gemm_tf32(
    const float* __restrict__ x, const float* __restrict__ t,
    const float* __restrict__ Wq, const float* __restrict__ bq,
    const float* __restrict__ Wk, const float* __restrict__ bk,
    const float* __restrict__ Wv, const float* __restrict__ bv,
    const float* __restrict__ Ws, const float* __restrict__ bs,
    int n)
{
    __shared__ float As[BM][BK + 4];
    __shared__ float Bs[BK][BN + 8];

    const int m0 = blockIdx.x * BM;
    const int slice = blockIdx.y;

    const float* Bmat; const float* bias; float* outp = nullptr;
    int voff = 0; bool packed = false;
    if (BW == 32) { Bmat = Ws; bias = bs; outp = g_skip; }
    else if (slice == 0)  { Bmat = Wq; bias = bq; outp = g_q; }
    else if (slice == 1)  { Bmat = Wk; bias = bk; packed = true; voff = 0; }
    else                  { Bmat = Wv; bias = bv; packed = true; voff = 4; }

    const int tid = threadIdx.x;
    const int lane = tid & 31;
    const int wid = tid >> 5;
    const int warp_m = wid & 3;
    const int warp_n = wid >> 2;
    const int g = lane >> 2;
    const int tig = lane & 3;

    constexpr int NI = (BW == 128) ? 8 : 4;
    float acc[2][NI][4];
    #pragma unroll
    for (int mi = 0; mi < 2; mi++)
        #pragma unroll
        for (int ni = 0; ni < NI; ni++)
            #pragma unroll
            for (int c = 0; c < 4; c++) acc[mi][ni][c] = 0.f;

    float4 ar[4];
    float4 br[4];

    const int a_row = tid >> 1;
    const int a_f4  = (tid & 1) * 4;
    const int b_col4 = tid & 31;

    auto loadA = [&](int k0) {
        const int mg = m0 + a_row;
        const int xbase = (k0 < 128 ? k0 : k0 - 128);
        float mult = 0.f;
        if (mg < n) mult = (k0 < 128) ? 1.f : t[mg];
        const float4* xr = (const float4*)&x[(size_t)(mg < n ? mg : 0) * 128 + xbase];
        #pragma unroll
        for (int i = 0; i < 4; i++) {
            float4 v = xr[a_f4 + i];
            ar[i].x = v.x * mult; ar[i].y = v.y * mult;
            ar[i].z = v.z * mult; ar[i].w = v.w * mult;
        }
    };
    auto storeA = [&]() {
        #pragma unroll
        for (int i = 0; i < 4; i++) {
            float4 v;
            v.x = __uint_as_float(f2tf(ar[i].x));
            v.y = __uint_as_float(f2tf(ar[i].y));
            v.z = __uint_as_float(f2tf(ar[i].z));
            v.w = __uint_as_float(f2tf(ar[i].w));
            *(float4*)&As[a_row][(a_f4 + i) * 4] = v;
        }
    };
    auto loadB = [&](int k0) {
        const int jj = b_col4 * 4;
        #pragma unroll
        for (int i = 0; i < 4; i++) {
            const int row = wid + i * 8;
            if (jj < BW) br[i] = *(const float4*)&Bmat[(size_t)(k0 + row) * BW + jj];
            else         br[i] = make_float4(0.f, 0.f, 0.f, 0.f);
        }
    };
    auto storeB = [&]() {
        const int jj = b_col4 * 4;
        #pragma unroll
        for (int i = 0; i < 4; i++) {
            const int row = wid + i * 8;
            float4 v;
            v.x = __uint_as_float(f2tf(br[i].x));
            v.y = __uint_as_float(f2tf(br[i].y));
            v.z = __uint_as_float(f2tf(br[i].z));
            v.w = __uint_as_float(f2tf(br[i].w));
            *(float4*)&Bs[row][jj] = v;
        }
    };

    loadA(0); loadB(0);
    storeA(); storeB();
    __syncthreads();

    for (int k0 = 0; k0 < 256; k0 += BK) {
        const bool has_next = (k0 + BK) < 256;
        if (has_next) { loadA(k0 + BK); loadB(k0 + BK); }

        if (BW == 128 || warp_n == 0) {
            #pragma unroll
            for (int ks = 0; ks < 4; ks++) {
                const int kk = ks * 8;
                unsigned afrag[2][4];
                #pragma unroll
                for (int mi = 0; mi < 2; mi++) {
                    const int r0 = warp_m * 32 + mi * 16 + g;
                    afrag[mi][0] = __float_as_uint(As[r0][kk + tig]);
                    afrag[mi][1] = __float_as_uint(As[r0 + 8][kk + tig]);
                    afrag[mi][2] = __float_as_uint(As[r0][kk + tig + 4]);
                    afrag[mi][3] = __float_as_uint(As[r0 + 8][kk + tig + 4]);
                }
                #pragma unroll
                for (int ni = 0; ni < NI; ni++) {
                    const int cb = warp_n * 64 + ni * 8 + g;
                    const unsigned b0 = __float_as_uint(Bs[kk + tig][cb]);
                    const unsigned b1 = __float_as_uint(Bs[kk + tig + 4][cb]);
                    mma_tf32(acc[0][ni], afrag[0], b0, b1);
                    mma_tf32(acc[1][ni], afrag[1], b0, b1);
                }
            }
        }
        __syncthreads();
        if (has_next) { storeA(); storeB(); __syncthreads(); }
    }

    if (BW == 32 && warp_n != 0) return;

    #pragma unroll
    for (int mi = 0; mi < 2; mi++) {
        const int row = warp_m * 32 + mi * 16 + g;
        #pragma unroll
        for (int ni = 0; ni < NI; ni++) {
            const int col = warp_n * 64 + ni * 8 + 2 * tig;
            if (col >= BW) continue;
            const float bb0 = bias[col];
            const float bb1 = bias[col + 1];
            const int mg0 = m0 + row;
            const int mg1 = m0 + row + 8;
            if (packed) {
                const int hidx = ((col >> 2) << 3) + (col & 3) + voff;
                if (mg0 < n) {
                    __half2 h = __floats2half2_rn(acc[mi][ni][0] + bb0,
                                                  acc[mi][ni][1] + bb1);
                    *(__half2*)&g_kvh[(size_t)mg0 * 256 + hidx] = h;
                }
                if (mg1 < n) {
                    __half2 h = __floats2half2_rn(acc[mi][ni][2] + bb0,
                                                  acc[mi][ni][3] + bb1);
                    *(__half2*)&g_kvh[(size_t)mg1 * 256 + hidx] = h;
                }
            } else {
                if (mg0 < n) {
                    float2 o; o.x = acc[mi][ni][0] + bb0; o.y = acc[mi][ni][1] + bb1;
                    *(float2*)&outp[(size_t)mg0 * BW + col] = o;
                }
                if (mg1 < n) {
                    float2 o; o.x = acc[mi][ni][2] + bb0; o.y = acc[mi][ni][3] + bb1;
                    *(float2*)&outp[(size_t)mg1 * BW + col] = o;
                }
            }
        }
    }
}

// ================= CSR build ===============================================
__global__ void count_deg(const int* __restrict__ ei, int nE) {
    const int e = blockIdx.x * blockDim.x + threadIdx.x;
    if (e < nE) atomicAdd(&g_deg[ei[nE + e]], 1);
}

#define SCAN_B 1024
__global__ void scan1(int n) {
    __shared__ int sh[SCAN_B];
    const int tid = threadIdx.x;
    const int i = blockIdx.x * SCAN_B + tid;
    const int v = (i < n) ? g_deg[i] : 0;
    sh[tid] = v;
    __syncthreads();
    #pragma unroll
    for (int off = 1; off < SCAN_B; off <<= 1) {
        int u = (tid >= off) ? sh[tid - off] : 0;
        __syncthreads();
        sh[tid] += u;
        __syncthreads();
    }
    if (i < n) g_off[i] = sh[tid] - v;   // exclusive
    if (tid == SCAN_B - 1) g_bsums[blockIdx.x] = sh[tid];
}

__global__ void scan2(int nb) {
    __shared__ int sh[64];
    const int tid = threadIdx.x;
    const int v = (tid < nb) ? g_bsums[tid] : 0;
    sh[tid] = v;
    __syncthreads();
    #pragma unroll
    for (int off = 1; off < 64; off <<= 1) {
        int u = (tid >= off) ? sh[tid - off] : 0;
        __syncthreads();
        sh[tid] += u;
        __syncthreads();
    }
    if (tid < nb) g_bsums[tid] = sh[tid] - v;  // exclusive
}

__global__ void scan3(int n) {
    const int i = blockIdx.x * SCAN_B + threadIdx.x;
    if (i < n && blockIdx.x > 0) g_off[i] += g_bsums[blockIdx.x];
}

// bump g_off[dst] directly: after this kernel g_off[dst] = inclusive end.
__global__ void scatter_csr(const int* __restrict__ ei,
                            const float* __restrict__ ew, int nE) {
    const int e = blockIdx.x * blockDim.x + threadIdx.x;
    if (e >= nE) return;
    const int src = ei[e];
    const int dst = ei[nE + e];
    const int pos = atomicAdd(&g_off[dst], 1);
    int2 sw;
    sw.x = src;
    sw.y = __float_as_int(ew[e]);
    g_csr[pos] = sw;
}

// ============ Fused node pass: persistent work-stealing warps ==============
// Each warp grabs node IDs from g_work (prefetching the next ID to hide the
// atomic's latency). Per-node math identical to R13 -> bit-identical output.
__global__ void __launch_bounds__(256) node_kernel(
    const float* __restrict__ x,
    const float* __restrict__ We, const float* __restrict__ be,
    const float* __restrict__ Wmlp, const float* __restrict__ bmlp,
    float* __restrict__ out, int n)
{
    __shared__ float w_sh[32 * 256];
    __shared__ float bm_sh[256];
    for (int i = threadIdx.x; i < 32 * 256; i += 256) w_sh[i] = Wmlp[i];
    if (threadIdx.x < 256) bm_sh[threadIdx.x] = bmlp[threadIdx.x];
    __syncthreads();

    const int lane = threadIdx.x & 31;

    const float4 We4 = ((const float4*)We)[lane];
    const float4 be4 = ((const float4*)be)[lane];
    const uint4* kvp = (const uint4*)g_kvh;

    // grab first node
    int cur = 0;
    if (lane == 0) cur = atomicAdd(&g_work, 1);
    cur = __shfl_sync(0xffffffffu, cur, 0);

    while (cur < n) {
        // prefetch next node id (latency hidden under this node's work)
        int nxt = 0;
        if (lane == 0) nxt = atomicAdd(&g_work, 1);
        nxt = __shfl_sync(0xffffffffu, nxt, 0);

        const int nn = cur;
        const float4 q4 = ((const float4*)g_q)[nn * 32 + lane];

        // per-head dots q.We and q.be (replicated across the head's 8 lanes)
        float qWe = q4.x * We4.x + q4.y * We4.y + q4.z * We4.z + q4.w * We4.w;
        float qbe = q4.x * be4.x + q4.y * be4.y + q4.z * be4.z + q4.w * be4.w;
        #pragma unroll
        for (int m = 1; m <= 4; m <<= 1) {
            qWe += __shfl_xor_sync(0xffffffffu, qWe, m);
            qbe += __shfl_xor_sync(0xffffffffu, qbe, m);
        }

        const int cnt = g_deg[nn];
        const int end = g_off[nn];          // inclusive end (scatter bumped it)
        const int beg = end - cnt;

        float4 macc = make_float4(0.f, 0.f, 0.f, 0.f);
        float dsum = 0.f;   // Sum p
        float wsum = 0.f;   // Sum wt*p

        int j = beg;
        const int lim = beg + (cnt & ~3);
        for (; j < lim; j += 4) {
            int2 sw[4];
            #pragma unroll
            for (int i = 0; i < 4; i++) sw[i] = g_csr[j + i];
            uint4 raw[4];
            #pragma unroll
            for (int i = 0; i < 4; i++) raw[i] = kvp[sw[i].x * 32 + lane];

            float s[4];
            #pragma unroll
            for (int i = 0; i < 4; i++) {
                const float2 k01 = __half22float2(*(const __half2*)&raw[i].x);
                const float2 k23 = __half22float2(*(const __half2*)&raw[i].y);
                s[i] = q4.x * k01.x + q4.y * k01.y + q4.z * k23.x + q4.w * k23.y;
            }
            #pragma unroll
            for (int i = 0; i < 4; i++) {
                s[i] += __shfl_xor_sync(0xffffffffu, s[i], 1);
                s[i] += __shfl_xor_sync(0xffffffffu, s[i], 2);
                s[i] += __shfl_xor_sync(0xffffffffu, s[i], 4);
            }
            #pragma unroll
            for (int i = 0; i < 4; i++) {
                const float2 v01 = __half22float2(*(const __half2*)&raw[i].z);
                const float2 v23 = __half22float2(*(const __half2*)&raw[i].w);
                const float wt = __int_as_float(sw[i].y);
                const float alpha = s[i] + fmaf(wt, qWe, qbe);
                const float p = __expf(alpha * 0.17677669529663689f);  // 1/sqrt(32)
                dsum += p;
                wsum = fmaf(wt, p, wsum);
                macc.x = fmaf(v01.x, p, macc.x);
                macc.y = fmaf(v01.y, p, macc.y);
                macc.z = fmaf(v23.x, p, macc.z);
                macc.w = fmaf(v23.y, p, macc.w);
            }
        }
        for (; j < end; j++) {
            const int2 sw = g_csr[j];
            const uint4 raw = kvp[sw.x * 32 + lane];
            const float2 k01 = __half22float2(*(const __half2*)&raw.x);
            const float2 k23 = __half22float2(*(const __half2*)&raw.y);
            const float2 v01 = __half22float2(*(const __half2*)&raw.z);
            const float2 v23 = __half22float2(*(const __half2*)&raw.w);
            float s = q4.x * k01.x + q4.y * k01.y + q4.z * k23.x + q4.w * k23.y;
            s += __shfl_xor_sync(0xffffffffu, s, 1);
            s += __shfl_xor_sync(0xffffffffu, s, 2);
            s += __shfl_xor_sync(0xffffffffu, s, 4);
            const float wt = __int_as_float(sw.y);
            const float alpha = s + fmaf(wt, qWe, qbe);
            const float p = __expf(alpha * 0.17677669529663689f);
            dsum += p;
            wsum = fmaf(wt, p, wsum);
            macc.x = fmaf(v01.x, p, macc.x);
            macc.y = fmaf(v01.y, p, macc.y);
            macc.z = fmaf(v23.x, p, macc.z);
            macc.w = fmaf(v23.y, p, macc.w);
        }

        // z = (Sum v p + We*Sum(wt p) + be*Sum p) / (Sum p + eps), per head
        const float inv = 1.f / (dsum + 1e-16f);
        float4 z4;
        z4.x = (macc.x + We4.x * wsum + be4.x * dsum) * inv;
        z4.y = (macc.y + We4.y * wsum + be4.y * dsum) * inv;
        z4.z = (macc.z + We4.z * wsum + be4.z * dsum) * inv;
        z4.w = (macc.w + We4.w * wsum + be4.w * dsum) * inv;

        #pragma unroll
        for (int m = 8; m <= 16; m <<= 1) {
            z4.x += __shfl_xor_sync(0xffffffffu, z4.x, m);
            z4.y += __shfl_xor_sync(0xffffffffu, z4.y, m);
            z4.z += __shfl_xor_sync(0xffffffffu, z4.z, m);
            z4.w += __shfl_xor_sync(0xffffffffu, z4.w, m);
        }

        const int u = lane & 7;
        const float4 sk = ((const float4*)g_skip)[nn * 8 + u];
        float4 y4;
        y4.x = tanhf(z4.x * 0.25f + sk.x);
        y4.y = tanhf(z4.y * 0.25f + sk.y);
        y4.z = tanhf(z4.z * 0.25f + sk.z);
        y4.w = tanhf(z4.w * 0.25f + sk.w);

        float accS[4] = {0.f, 0.f, 0.f, 0.f};
        float accH[4] = {0.f, 0.f, 0.f, 0.f};
        #pragma unroll
        for (int uu = 0; uu < 8; uu++) {
            const float b0 = __shfl_sync(0xffffffffu, y4.x, uu);
            const float b1 = __shfl_sync(0xffffffffu, y4.y, uu);
            const float b2 = __shfl_sync(0xffffffffu, y4.z, uu);
            const float b3 = __shfl_sync(0xffffffffu, y4.w, uu);
            const int d0 = 4 * uu;
            #pragma unroll
            for (int k = 0; k < 4; k++) {
                const int c = lane + 32 * k;
                accS[k] = fmaf(b0, w_sh[(d0 + 0) * 256 + c], accS[k]);
                accS[k] = fmaf(b1, w_sh[(d0 + 1) * 256 + c], accS[k]);
                accS[k] = fmaf(b2, w_sh[(d0 + 2) * 256 + c], accS[k]);
                accS[k] = fmaf(b3, w_sh[(d0 + 3) * 256 + c], accS[k]);
                accH[k] = fmaf(b0, w_sh[(d0 + 0) * 256 + 128 + c], accH[k]);
                accH[k] = fmaf(b1, w_sh[(d0 + 1) * 256 + 128 + c], accH[k]);
                accH[k] = fmaf(b2, w_sh[(d0 + 2) * 256 + 128 + c], accH[k]);
                accH[k] = fmaf(b3, w_sh[(d0 + 3) * 256 + 128 + c], accH[k]);
            }
        }
        #pragma unroll
        for (int k = 0; k < 4; k++) {
            const int c = lane + 32 * k;
            const float sc = tanhf(accS[k] + bm_sh[c]);
            const float sh = tanhf(accH[k] + bm_sh[128 + c]);
            out[(size_t)nn * 128 + c] = fmaf(x[(size_t)nn * 128 + c], sc, sh);
        }

        cur = nxt;
    }
}

// ================= launch ==================================================
extern "C" void kernel_launch(void* const* d_in, const int* in_sizes, int n_in,
                              void* d_out, int out_size)
{
    const float* x     = (const float*)d_in[0];
    const float* t     = (const float*)d_in[1];
    const int*   ei    = (const int*)  d_in[2];
    const float* ew    = (const float*)d_in[3];
    const float* Wq    = (const float*)d_in[4];
    const float* bq    = (const float*)d_in[5];
    const float* Wk    = (const float*)d_in[6];
    const float* bk    = (const float*)d_in[7];
    const float* Wv    = (const float*)d_in[8];
    const float* bv    = (const float*)d_in[9];
    const float* We    = (const float*)d_in[10];
    const float* be    = (const float*)d_in[11];
    const float* Wskip = (const float*)d_in[12];
    const float* bskip = (const float*)d_in[13];
    const float* Wmlp  = (const float*)d_in[14];
    const float* bmlp  = (const float*)d_in[15];
    float* out = (float*)d_out;

    const int n  = in_sizes[0] / 128;
    const int nE = in_sizes[3];

    // one-time side stream + fork/join events (same work every call)
    static cudaStream_t sB = nullptr;
    static cudaEvent_t evFork = nullptr, evJoin = nullptr;
    if (sB == nullptr) {
        cudaStreamCreateWithFlags(&sB, cudaStreamNonBlocking);
        cudaEventCreateWithFlags(&evFork, cudaEventDisableTiming);
        cudaEventCreateWithFlags(&evJoin, cudaEventDisableTiming);
    }

    void *degPtr = nullptr, *workPtr = nullptr;
    cudaGetSymbolAddress(&degPtr, g_deg);
    cudaGetSymbolAddress(&workPtr, g_work);

    // reset work cursor (tiny, main stream, precedes node_kernel)
    cudaMemsetAsync(workPtr, 0, sizeof(int));

    // ---- fork: CSR build on side stream, GEMM on main stream -------------
    cudaEventRecord(evFork, 0);
    cudaStreamWaitEvent(sB, evFork, 0);

    cudaMemsetAsync(degPtr, 0, (size_t)n * sizeof(int), sB);
    count_deg<<<(nE + 255) / 256, 256, 0, sB>>>(ei, nE);
    const int nb = (n + SCAN_B - 1) / SCAN_B;
    scan1<<<nb, SCAN_B, 0, sB>>>(n);
    scan2<<<1, 64, 0, sB>>>(nb);
    scan3<<<nb, SCAN_B, 0, sB>>>(n);
    scatter_csr<<<(nE + 255) / 256, 256, 0, sB>>>(ei, ew, nE);
    cudaEventRecord(evJoin, sB);

    // main stream: q,k,v (BW=128, 3 slices) then cheap skip slice (BW=32)
    const int gm = (n + BM - 1) / BM;
    gemm_tf32<128><<<dim3(gm, 3), 256>>>(x, t, Wq, bq, Wk, bk, Wv, bv,
                                         Wskip, bskip, n);
    gemm_tf32<32><<<dim3(gm, 1), 256>>>(x, t, Wq, bq, Wk, bk, Wv, bv,
                                        Wskip, bskip, n);

    // ---- join, then fused attention + epilogue (persistent grid) ---------
    cudaStreamWaitEvent(0, evJoin, 0);
    node_kernel<<<148 * 6, 256>>>(x, We, be, Wmlp, bmlp, out, n);
}

// round 15
// speedup vs baseline: 1.1694x; 1.0071x over previous
#include <cuda_runtime.h>
#include <cuda_fp16.h>
#include <math.h>

#define N_NODES 50000
#define N_EDGES 800000

// ---------------- scratch (no cudaMalloc allowed) ----------------
__device__ float  g_q[N_NODES * 128];
__device__ __half g_kvh[N_NODES * 256];  // packed per row: [k(4)|v(4)] x 32 lanes
__device__ float  g_skip[N_NODES * 32];
__device__ int    g_deg[N_NODES];
__device__ int    g_off[N_NODES];       // exclusive prefix; after scatter = inclusive end
__device__ int2   g_csr[N_EDGES];       // (src, bitcast(weight)) grouped by dst
__device__ int    g_bsums[64];
__device__ int    g_work;               // work-stealing cursor for node pass

// ================= tf32 tensor-core GEMM (proven R2/R7 style) ==============
#define BM 128
#define BN 128
#define BK 32

__device__ __forceinline__ unsigned f2tf(float x) {
    unsigned r;
    asm("cvt.rna.tf32.f32 %0, %1;" : "=r"(r) : "f"(x));
    return r;
}

__device__ __forceinline__ void mma_tf32(float* c, const unsigned* a,
                                         unsigned b0, unsigned b1) {
    asm volatile(
        "mma.sync.aligned.m16n8k8.row.col.f32.tf32.tf32.f32 "
        "{%0,%1,%2,%3}, {%4,%5,%6,%7}, {%8,%9}, {%0,%1,%2,%3};\n"
        : "+f"(c[0]), "+f"(c[1]), "+f"(c[2]), "+f"(c[3])
        : "r"(a[0]), "r"(a[1]), "r"(a[2]), "r"(a[3]), "r"(b0), "r"(b1));
}

// BW=128: slices 0..2 (q, kv-packed). BW=32: skip slice, only warp_n==0,
// NI=4 ni-tiles (cols 0..31) — 1/4 of the MMA work per CTA.
template<int BW>
__global__ void __launch_bounds__(256, 2) gemm_tf32(
    const float* __restrict__ x, const float* __restrict__ t,
    const float* __restrict__ Wq, const float* __restrict__ bq,
    const float* __restrict__ Wk, const float* __restrict__ bk,
    const float* __restrict__ Wv, const float* __restrict__ bv,
    const float* __restrict__ Ws, const float* __restrict__ bs,
    int n)
{
    __shared__ float As[BM][BK + 4];
    __shared__ float Bs[BK][BN + 8];

    const int m0 = blockIdx.x * BM;
    const int slice = blockIdx.y;

    const float* Bmat; const float* bias; float* outp = nullptr;
    int voff = 0; bool packed = false;
    if (BW == 32) { Bmat = Ws; bias = bs; outp = g_skip; }
    else if (slice == 0)  { Bmat = Wq; bias = bq; outp = g_q; }
    else if (slice == 1)  { Bmat = Wk; bias = bk; packed = true; voff = 0; }
    else                  { Bmat = Wv; bias = bv; packed = true; voff = 4; }

    const int tid = threadIdx.x;
    const int lane = tid & 31;
    const int wid = tid >> 5;
    const int warp_m = wid & 3;
    const int warp_n = wid >> 2;
    const int g = lane >> 2;
    const int tig = lane & 3;

    constexpr int NI = (BW == 128) ? 8 : 4;
    float acc[2][NI][4];
    #pragma unroll
    for (int mi = 0; mi < 2; mi++)
        #pragma unroll
        for (int ni = 0; ni < NI; ni++)
            #pragma unroll
            for (int c = 0; c < 4; c++) acc[mi][ni][c] = 0.f;

    float4 ar[4];
    float4 br[4];

    const int a_row = tid >> 1;
    const int a_f4  = (tid & 1) * 4;
    const int b_col4 = tid & 31;

    auto loadA = [&](int k0) {
        const int mg = m0 + a_row;
        const int xbase = (k0 < 128 ? k0 : k0 - 128);
        float mult = 0.f;
        if (mg < n) mult = (k0 < 128) ? 1.f : t[mg];
        const float4* xr = (const float4*)&x[(size_t)(mg < n ? mg : 0) * 128 + xbase];
        #pragma unroll
        for (int i = 0; i < 4; i++) {
            float4 v = xr[a_f4 + i];
            ar[i].x = v.x * mult; ar[i].y = v.y * mult;
            ar[i].z = v.z * mult; ar[i].w = v.w * mult;
        }
    };
    auto storeA = [&]() {
        #pragma unroll
        for (int i = 0; i < 4; i++) {
            float4 v;
            v.x = __uint_as_float(f2tf(ar[i].x));
            v.y = __uint_as_float(f2tf(ar[i].y));
            v.z = __uint_as_float(f2tf(ar[i].z));
            v.w = __uint_as_float(f2tf(ar[i].w));
            *(float4*)&As[a_row][(a_f4 + i) * 4] = v;
        }
    };
    auto loadB = [&](int k0) {
        const int jj = b_col4 * 4;
        #pragma unroll
        for (int i = 0; i < 4; i++) {
            const int row = wid + i * 8;
            if (jj < BW) br[i] = *(const float4*)&Bmat[(size_t)(k0 + row) * BW + jj];
            else         br[i] = make_float4(0.f, 0.f, 0.f, 0.f);
        }
    };
    auto storeB = [&]() {
        const int jj = b_col4 * 4;
        #pragma unroll
        for (int i = 0; i < 4; i++) {
            const int row = wid + i * 8;
            float4 v;
            v.x = __uint_as_float(f2tf(br[i].x));
            v.y = __uint_as_float(f2tf(br[i].y));
            v.z = __uint_as_float(f2tf(br[i].z));
            v.w = __uint_as_float(f2tf(br[i].w));
            *(float4*)&Bs[row][jj] = v;
        }
    };

    loadA(0); loadB(0);
    storeA(); storeB();
    __syncthreads();

    for (int k0 = 0; k0 < 256; k0 += BK) {
        const bool has_next = (k0 + BK) < 256;
        if (has_next) { loadA(k0 + BK); loadB(k0 + BK); }

        if (BW == 128 || warp_n == 0) {
            #pragma unroll
            for (int ks = 0; ks < 4; ks++) {
                const int kk = ks * 8;
                unsigned afrag[2][4];
                #pragma unroll
                for (int mi = 0; mi < 2; mi++) {
                    const int r0 = warp_m * 32 + mi * 16 + g;
                    afrag[mi][0] = __float_as_uint(As[r0][kk + tig]);
                    afrag[mi][1] = __float_as_uint(As[r0 + 8][kk + tig]);
                    afrag[mi][2] = __float_as_uint(As[r0][kk + tig + 4]);
                    afrag[mi][3] = __float_as_uint(As[r0 + 8][kk + tig + 4]);
                }
                #pragma unroll
                for (int ni = 0; ni < NI; ni++) {
                    const int cb = warp_n * 64 + ni * 8 + g;
                    const unsigned b0 = __float_as_uint(Bs[kk + tig][cb]);
                    const unsigned b1 = __float_as_uint(Bs[kk + tig + 4][cb]);
                    mma_tf32(acc[0][ni], afrag[0], b0, b1);
                    mma_tf32(acc[1][ni], afrag[1], b0, b1);
                }
            }
        }
        __syncthreads();
        if (has_next) { storeA(); storeB(); __syncthreads(); }
    }

    if (BW == 32 && warp_n != 0) return;

    #pragma unroll
    for (int mi = 0; mi < 2; mi++) {
        const int row = warp_m * 32 + mi * 16 + g;
        #pragma unroll
        for (int ni = 0; ni < NI; ni++) {
            const int col = warp_n * 64 + ni * 8 + 2 * tig;
            if (col >= BW) continue;
            const float bb0 = bias[col];
            const float bb1 = bias[col + 1];
            const int mg0 = m0 + row;
            const int mg1 = m0 + row + 8;
            if (packed) {
                const int hidx = ((col >> 2) << 3) + (col & 3) + voff;
                if (mg0 < n) {
                    __half2 h = __floats2half2_rn(acc[mi][ni][0] + bb0,
                                                  acc[mi][ni][1] + bb1);
                    *(__half2*)&g_kvh[(size_t)mg0 * 256 + hidx] = h;
                }
                if (mg1 < n) {
                    __half2 h = __floats2half2_rn(acc[mi][ni][2] + bb0,
                                                  acc[mi][ni][3] + bb1);
                    *(__half2*)&g_kvh[(size_t)mg1 * 256 + hidx] = h;
                }
            } else {
                if (mg0 < n) {
                    float2 o; o.x = acc[mi][ni][0] + bb0; o.y = acc[mi][ni][1] + bb1;
                    *(float2*)&outp[(size_t)mg0 * BW + col] = o;
                }
                if (mg1 < n) {
                    float2 o; o.x = acc[mi][ni][2] + bb0; o.y = acc[mi][ni][3] + bb1;
                    *(float2*)&outp[(size_t)mg1 * BW + col] = o;
                }
            }
        }
    }
}

// ================= CSR build ===============================================
__global__ void count_deg(const int* __restrict__ ei, int nE) {
    const int e = blockIdx.x * blockDim.x + threadIdx.x;
    if (e < nE) atomicAdd(&g_deg[ei[nE + e]], 1);
}

#define SCAN_B 1024
__global__ void scan1(int n) {
    __shared__ int sh[SCAN_B];
    const int tid = threadIdx.x;
    const int i = blockIdx.x * SCAN_B + tid;
    const int v = (i < n) ? g_deg[i] : 0;
    sh[tid] = v;
    __syncthreads();
    #pragma unroll
    for (int off = 1; off < SCAN_B; off <<= 1) {
        int u = (tid >= off) ? sh[tid - off] : 0;
        __syncthreads();
        sh[tid] += u;
        __syncthreads();
    }
    if (i < n) g_off[i] = sh[tid] - v;   // exclusive
    if (tid == SCAN_B - 1) g_bsums[blockIdx.x] = sh[tid];
}

__global__ void scan2(int nb) {
    __shared__ int sh[64];
    const int tid = threadIdx.x;
    const int v = (tid < nb) ? g_bsums[tid] : 0;
    sh[tid] = v;
    __syncthreads();
    #pragma unroll
    for (int off = 1; off < 64; off <<= 1) {
        int u = (tid >= off) ? sh[tid - off] : 0;
        __syncthreads();
        sh[tid] += u;
        __syncthreads();
    }
    if (tid < nb) g_bsums[tid] = sh[tid] - v;  // exclusive
}

__global__ void scan3(int n) {
    const int i = blockIdx.x * SCAN_B + threadIdx.x;
    if (i < n && blockIdx.x > 0) g_off[i] += g_bsums[blockIdx.x];
}

// bump g_off[dst] directly: after this kernel g_off[dst] = inclusive end.
__global__ void scatter_csr(const int* __restrict__ ei,
                            const float* __restrict__ ew, int nE) {
    const int e = blockIdx.x * blockDim.x + threadIdx.x;
    if (e >= nE) return;
    const int src = ei[e];
    const int dst = ei[nE + e];
    const int pos = atomicAdd(&g_off[dst], 1);
    int2 sw;
    sw.x = src;
    sw.y = __float_as_int(ew[e]);
    g_csr[pos] = sw;
}

// ============ Fused node pass: persistent work-stealing warps ==============
// Each warp grabs node IDs from g_work, prefetching the next node's id AND
// its metadata (deg/off/q) to hide the serial head latency of each node.
__global__ void __launch_bounds__(256) node_kernel(
    const float* __restrict__ x,
    const float* __restrict__ We, const float* __restrict__ be,
    const float* __restrict__ Wmlp, const float* __restrict__ bmlp,
    float* __restrict__ out, int n)
{
    __shared__ float w_sh[32 * 256];
    __shared__ float bm_sh[256];
    for (int i = threadIdx.x; i < 32 * 256; i += 256) w_sh[i] = Wmlp[i];
    if (threadIdx.x < 256) bm_sh[threadIdx.x] = bmlp[threadIdx.x];
    __syncthreads();

    const int lane = threadIdx.x & 31;

    const float4 We4 = ((const float4*)We)[lane];
    const float4 be4 = ((const float4*)be)[lane];
    const uint4* kvp = (const uint4*)g_kvh;

    // grab first node + its metadata
    int cur = 0;
    if (lane == 0) cur = atomicAdd(&g_work, 1);
    cur = __shfl_sync(0xffffffffu, cur, 0);

    int curCnt = 0, curEnd = 0;
    float4 curQ = make_float4(0.f, 0.f, 0.f, 0.f);
    if (cur < n) {
        curCnt = g_deg[cur];
        curEnd = g_off[cur];
        curQ = ((const float4*)g_q)[cur * 32 + lane];
    }

    while (cur < n) {
        // prefetch next node id + metadata (hidden under this node's work)
        int nxt = 0;
        if (lane == 0) nxt = atomicAdd(&g_work, 1);
        nxt = __shfl_sync(0xffffffffu, nxt, 0);
        int nxtCnt = 0, nxtEnd = 0;
        float4 nxtQ = make_float4(0.f, 0.f, 0.f, 0.f);
        if (nxt < n) {
            nxtCnt = g_deg[nxt];
            nxtEnd = g_off[nxt];
            nxtQ = ((const float4*)g_q)[nxt * 32 + lane];
        }

        const int nn = cur;
        const float4 q4 = curQ;

        // per-head dots q.We and q.be (replicated across the head's 8 lanes)
        float qWe = q4.x * We4.x + q4.y * We4.y + q4.z * We4.z + q4.w * We4.w;
        float qbe = q4.x * be4.x + q4.y * be4.y + q4.z * be4.z + q4.w * be4.w;
        #pragma unroll
        for (int m = 1; m <= 4; m <<= 1) {
            qWe += __shfl_xor_sync(0xffffffffu, qWe, m);
            qbe += __shfl_xor_sync(0xffffffffu, qbe, m);
        }

        const int cnt = curCnt;
        const int end = curEnd;
        const int beg = end - cnt;

        float4 macc = make_float4(0.f, 0.f, 0.f, 0.f);
        float dsum = 0.f;   // Sum p
        float wsum = 0.f;   // Sum wt*p

        int j = beg;
        const int lim = beg + (cnt & ~3);
        for (; j < lim; j += 4) {
            int2 sw[4];
            #pragma unroll
            for (int i = 0; i < 4; i++) sw[i] = g_csr[j + i];
            uint4 raw[4];
            #pragma unroll
            for (int i = 0; i < 4; i++) raw[i] = kvp[sw[i].x * 32 + lane];

            float s[4];
            #pragma unroll
            for (int i = 0; i < 4; i++) {
                const float2 k01 = __half22float2(*(const __half2*)&raw[i].x);
                const float2 k23 = __half22float2(*(const __half2*)&raw[i].y);
                s[i] = q4.x * k01.x + q4.y * k01.y + q4.z * k23.x + q4.w * k23.y;
            }
            #pragma unroll
            for (int i = 0; i < 4; i++) {
                s[i] += __shfl_xor_sync(0xffffffffu, s[i], 1);
                s[i] += __shfl_xor_sync(0xffffffffu, s[i], 2);
                s[i] += __shfl_xor_sync(0xffffffffu, s[i], 4);
            }
            #pragma unroll
            for (int i = 0; i < 4; i++) {
                const float2 v01 = __half22float2(*(const __half2*)&raw[i].z);
                const float2 v23 = __half22float2(*(const __half2*)&raw[i].w);
                const float wt = __int_as_float(sw[i].y);
                const float alpha = s[i] + fmaf(wt, qWe, qbe);
                const float p = __expf(alpha * 0.17677669529663689f);  // 1/sqrt(32)
                dsum += p;
                wsum = fmaf(wt, p, wsum);
                macc.x = fmaf(v01.x, p, macc.x);
                macc.y = fmaf(v01.y, p, macc.y);
                macc.z = fmaf(v23.x, p, macc.z);
                macc.w = fmaf(v23.y, p, macc.w);
            }
        }
        for (; j < end; j++) {
            const int2 sw = g_csr[j];
            const uint4 raw = kvp[sw.x * 32 + lane];
            const float2 k01 = __half22float2(*(const __half2*)&raw.x);
            const float2 k23 = __half22float2(*(const __half2*)&raw.y);
            const float2 v01 = __half22float2(*(const __half2*)&raw.z);
            const float2 v23 = __half22float2(*(const __half2*)&raw.w);
            float s = q4.x * k01.x + q4.y * k01.y + q4.z * k23.x + q4.w * k23.y;
            s += __shfl_xor_sync(0xffffffffu, s, 1);
            s += __shfl_xor_sync(0xffffffffu, s, 2);
            s += __shfl_xor_sync(0xffffffffu, s, 4);
            const float wt = __int_as_float(sw.y);
            const float alpha = s + fmaf(wt, qWe, qbe);
            const float p = __expf(alpha * 0.17677669529663689f);
            dsum += p;
            wsum = fmaf(wt, p, wsum);
            macc.x = fmaf(v01.x, p, macc.x);
            macc.y = fmaf(v01.y, p, macc.y);
            macc.z = fmaf(v23.x, p, macc.z);
            macc.w = fmaf(v23.y, p, macc.w);
        }

        // z = (Sum v p + We*Sum(wt p) + be*Sum p) / (Sum p + eps), per head
        const float inv = 1.f / (dsum + 1e-16f);
        float4 z4;
        z4.x = (macc.x + We4.x * wsum + be4.x * dsum) * inv;
        z4.y = (macc.y + We4.y * wsum + be4.y * dsum) * inv;
        z4.z = (macc.z + We4.z * wsum + be4.z * dsum) * inv;
        z4.w = (macc.w + We4.w * wsum + be4.w * dsum) * inv;

        #pragma unroll
        for (int m = 8; m <= 16; m <<= 1) {
            z4.x += __shfl_xor_sync(0xffffffffu, z4.x, m);
            z4.y += __shfl_xor_sync(0xffffffffu, z4.y, m);
            z4.z += __shfl_xor_sync(0xffffffffu, z4.z, m);
            z4.w += __shfl_xor_sync(0xffffffffu, z4.w, m);
        }

        const int u = lane & 7;
        const float4 sk = ((const float4*)g_skip)[nn * 8 + u];
        float4 y4;
        y4.x = tanhf(z4.x * 0.25f + sk.x);
        y4.y = tanhf(z4.y * 0.25f + sk.y);
        y4.z = tanhf(z4.z * 0.25f + sk.z);
        y4.w = tanhf(z4.w * 0.25f + sk.w);

        float accS[4] = {0.f, 0.f, 0.f, 0.f};
        float accH[4] = {0.f, 0.f, 0.f, 0.f};
        #pragma unroll
        for (int uu = 0; uu < 8; uu++) {
            const float b0 = __shfl_sync(0xffffffffu, y4.x, uu);
            const float b1 = __shfl_sync(0xffffffffu, y4.y, uu);
            const float b2 = __shfl_sync(0xffffffffu, y4.z, uu);
            const float b3 = __shfl_sync(0xffffffffu, y4.w, uu);
            const int d0 = 4 * uu;
            #pragma unroll
            for (int k = 0; k < 4; k++) {
                const int c = lane + 32 * k;
                accS[k] = fmaf(b0, w_sh[(d0 + 0) * 256 + c], accS[k]);
                accS[k] = fmaf(b1, w_sh[(d0 + 1) * 256 + c], accS[k]);
                accS[k] = fmaf(b2, w_sh[(d0 + 2) * 256 + c], accS[k]);
                accS[k] = fmaf(b3, w_sh[(d0 + 3) * 256 + c], accS[k]);
                accH[k] = fmaf(b0, w_sh[(d0 + 0) * 256 + 128 + c], accH[k]);
                accH[k] = fmaf(b1, w_sh[(d0 + 1) * 256 + 128 + c], accH[k]);
                accH[k] = fmaf(b2, w_sh[(d0 + 2) * 256 + 128 + c], accH[k]);
                accH[k] = fmaf(b3, w_sh[(d0 + 3) * 256 + 128 + c], accH[k]);
            }
        }
        #pragma unroll
        for (int k = 0; k < 4; k++) {
            const int c = lane + 32 * k;
            const float sc = tanhf(accS[k] + bm_sh[c]);
            const float sh = tanhf(accH[k] + bm_sh[128 + c]);
            out[(size_t)nn * 128 + c] = fmaf(x[(size_t)nn * 128 + c], sc, sh);
        }

        cur = nxt; curCnt = nxtCnt; curEnd = nxtEnd; curQ = nxtQ;
    }
}

// ================= launch ==================================================
extern "C" void kernel_launch(void* const* d_in, const int* in_sizes, int n_in,
                              void* d_out, int out_size)
{
    const float* x     = (const float*)d_in[0];
    const float* t     = (const float*)d_in[1];
    const int*   ei    = (const int*)  d_in[2];
    const float* ew    = (const float*)d_in[3];
    const float* Wq    = (const float*)d_in[4];
    const float* bq    = (const float*)d_in[5];
    const float* Wk    = (const float*)d_in[6];
    const float* bk    = (const float*)d_in[7];
    const float* Wv    = (const float*)d_in[8];
    const float* bv    = (const float*)d_in[9];
    const float* We    = (const float*)d_in[10];
    const float* be    = (const float*)d_in[11];
    const float* Wskip = (const float*)d_in[12];
    const float* bskip = (const float*)d_in[13];
    const float* Wmlp  = (const float*)d_in[14];
    const float* bmlp  = (const float*)d_in[15];
    float* out = (float*)d_out;

    const int n  = in_sizes[0] / 128;
    const int nE = in_sizes[3];

    // one-time side stream + fork/join events (same work every call)
    static cudaStream_t sB = nullptr;
    static cudaEvent_t evFork = nullptr, evJoin = nullptr;
    if (sB == nullptr) {
        cudaStreamCreateWithFlags(&sB, cudaStreamNonBlocking);
        cudaEventCreateWithFlags(&evFork, cudaEventDisableTiming);
        cudaEventCreateWithFlags(&evJoin, cudaEventDisableTiming);
    }

    void *degPtr = nullptr, *workPtr = nullptr;
    cudaGetSymbolAddress(&degPtr, g_deg);
    cudaGetSymbolAddress(&workPtr, g_work);

    // reset work cursor (tiny, main stream, precedes node_kernel)
    cudaMemsetAsync(workPtr, 0, sizeof(int));

    // ---- fork: skip GEMM first, then CSR build on side stream ------------
    cudaEventRecord(evFork, 0);
    cudaStreamWaitEvent(sB, evFork, 0);

    const int gm = (n + BM - 1) / BM;
    gemm_tf32<32><<<dim3(gm, 1), 256, 0, sB>>>(x, t, Wq, bq, Wk, bk, Wv, bv,
                                               Wskip, bskip, n);
    cudaMemsetAsync(degPtr, 0, (size_t)n * sizeof(int), sB);
    count_deg<<<(nE + 255) / 256, 256, 0, sB>>>(ei, nE);
    const int nb = (n + SCAN_B - 1) / SCAN_B;
    scan1<<<nb, SCAN_B, 0, sB>>>(n);
    scan2<<<1, 64, 0, sB>>>(nb);
    scan3<<<nb, SCAN_B, 0, sB>>>(n);
    scatter_csr<<<(nE + 255) / 256, 256, 0, sB>>>(ei, ew, nE);
    cudaEventRecord(evJoin, sB);

    // main stream: q,k,v (BW=128, 3 slices)
    gemm_tf32<128><<<dim3(gm, 3), 256>>>(x, t, Wq, bq, Wk, bk, Wv, bv,
                                         Wskip, bskip, n);

    // ---- join, then fused attention + epilogue (persistent grid) ---------
    cudaStreamWaitEvent(0, evJoin, 0);
    node_kernel<<<148 * 6, 256>>>(x, We, be, Wmlp, bmlp, out, n);
}

// round 16
// speedup vs baseline: 1.1874x; 1.0153x over previous
#include <cuda_runtime.h>
#include <cuda_fp16.h>
#include <math.h>

#define N_NODES 50000
#define N_EDGES 800000

// ---------------- scratch (no cudaMalloc allowed) ----------------
__device__ float  g_q[N_NODES * 128];
__device__ __half g_kvh[N_NODES * 256];  // packed per row: [k(4)|v(4)] x 32 lanes
__device__ float  g_skip[N_NODES * 32];
__device__ int    g_deg[N_NODES];
__device__ int    g_off[N_NODES];       // exclusive prefix; after scatter = inclusive end
__device__ int2   g_csr[N_EDGES];       // (src, bitcast(weight)) grouped by dst
__device__ int    g_bsums[64];
__device__ int    g_work;               // work-stealing cursor for node pass

// ================= tf32 tensor-core GEMM (proven R2/R7 style) ==============
#define BM 128
#define BN 128
#define BK 32

__device__ __forceinline__ unsigned f2tf(float x) {
    unsigned r;
    asm("cvt.rna.tf32.f32 %0, %1;" : "=r"(r) : "f"(x));
    return r;
}

__device__ __forceinline__ void mma_tf32(float* c, const unsigned* a,
                                         unsigned b0, unsigned b1) {
    asm volatile(
        "mma.sync.aligned.m16n8k8.row.col.f32.tf32.tf32.f32 "
        "{%0,%1,%2,%3}, {%4,%5,%6,%7}, {%8,%9}, {%0,%1,%2,%3};\n"
        : "+f"(c[0]), "+f"(c[1]), "+f"(c[2]), "+f"(c[3])
        : "r"(a[0]), "r"(a[1]), "r"(a[2]), "r"(a[3]), "r"(b0), "r"(b1));
}

// BW=128: slices 0..2 (q, kv-packed). BW=32: skip slice, only warp_n==0,
// NI=4 ni-tiles (cols 0..31) — 1/4 of the MMA work per CTA.
template<int BW>
__global__ void __launch_bounds__(256, 2) gemm_tf32(
    const float* __restrict__ x, const float* __restrict__ t,
    const float* __restrict__ Wq, const float* __restrict__ bq,
    const float* __restrict__ Wk, const float* __restrict__ bk,
    const float* __restrict__ Wv, const float* __restrict__ bv,
    const float* __restrict__ Ws, const float* __restrict__ bs,
    int n)
{
    __shared__ float As[BM][BK + 4];
    __shared__ float Bs[BK][BN + 8];

    const int m0 = blockIdx.x * BM;
    const int slice = blockIdx.y;

    const float* Bmat; const float* bias; float* outp = nullptr;
    int voff = 0; bool packed = false;
    if (BW == 32) { Bmat = Ws; bias = bs; outp = g_skip; }
    else if (slice == 0)  { Bmat = Wq; bias = bq; outp = g_q; }
    else if (slice == 1)  { Bmat = Wk; bias = bk; packed = true; voff = 0; }
    else                  { Bmat = Wv; bias = bv; packed = true; voff = 4; }

    const int tid = threadIdx.x;
    const int lane = tid & 31;
    const int wid = tid >> 5;
    const int warp_m = wid & 3;
    const int warp_n = wid >> 2;
    const int g = lane >> 2;
    const int tig = lane & 3;

    constexpr int NI = (BW == 128) ? 8 : 4;
    float acc[2][NI][4];
    #pragma unroll
    for (int mi = 0; mi < 2; mi++)
        #pragma unroll
        for (int ni = 0; ni < NI; ni++)
            #pragma unroll
            for (int c = 0; c < 4; c++) acc[mi][ni][c] = 0.f;

    float4 ar[4];
    float4 br[4];

    const int a_row = tid >> 1;
    const int a_f4  = (tid & 1) * 4;
    const int b_col4 = tid & 31;

    auto loadA = [&](int k0) {
        const int mg = m0 + a_row;
        const int xbase = (k0 < 128 ? k0 : k0 - 128);
        float mult = 0.f;
        if (mg < n) mult = (k0 < 128) ? 1.f : t[mg];
        const float4* xr = (const float4*)&x[(size_t)(mg < n ? mg : 0) * 128 + xbase];
        #pragma unroll
        for (int i = 0; i < 4; i++) {
            float4 v = xr[a_f4 + i];
            ar[i].x = v.x * mult; ar[i].y = v.y * mult;
            ar[i].z = v.z * mult; ar[i].w = v.w * mult;
        }
    };
    auto storeA = [&]() {
        #pragma unroll
        for (int i = 0; i < 4; i++) {
            float4 v;
            v.x = __uint_as_float(f2tf(ar[i].x));
            v.y = __uint_as_float(f2tf(ar[i].y));
            v.z = __uint_as_float(f2tf(ar[i].z));
            v.w = __uint_as_float(f2tf(ar[i].w));
            *(float4*)&As[a_row][(a_f4 + i) * 4] = v;
        }
    };
    auto loadB = [&](int k0) {
        const int jj = b_col4 * 4;
        #pragma unroll
        for (int i = 0; i < 4; i++) {
            const int row = wid + i * 8;
            if (jj < BW) br[i] = *(const float4*)&Bmat[(size_t)(k0 + row) * BW + jj];
            else         br[i] = make_float4(0.f, 0.f, 0.f, 0.f);
        }
    };
    auto storeB = [&]() {
        const int jj = b_col4 * 4;
        #pragma unroll
        for (int i = 0; i < 4; i++) {
            const int row = wid + i * 8;
            float4 v;
            v.x = __uint_as_float(f2tf(br[i].x));
            v.y = __uint_as_float(f2tf(br[i].y));
            v.z = __uint_as_float(f2tf(br[i].z));
            v.w = __uint_as_float(f2tf(br[i].w));
            *(float4*)&Bs[row][jj] = v;
        }
    };

    loadA(0); loadB(0);
    storeA(); storeB();
    __syncthreads();

    for (int k0 = 0; k0 < 256; k0 += BK) {
        const bool has_next = (k0 + BK) < 256;
        if (has_next) { loadA(k0 + BK); loadB(k0 + BK); }

        if (BW == 128 || warp_n == 0) {
            #pragma unroll
            for (int ks = 0; ks < 4; ks++) {
                const int kk = ks * 8;
                unsigned afrag[2][4];
                #pragma unroll
                for (int mi = 0; mi < 2; mi++) {
                    const int r0 = warp_m * 32 + mi * 16 + g;
                    afrag[mi][0] = __float_as_uint(As[r0][kk + tig]);
                    afrag[mi][1] = __float_as_uint(As[r0 + 8][kk + tig]);
                    afrag[mi][2] = __float_as_uint(As[r0][kk + tig + 4]);
                    afrag[mi][3] = __float_as_uint(As[r0 + 8][kk + tig + 4]);
                }
                #pragma unroll
                for (int ni = 0; ni < NI; ni++) {
                    const int cb = warp_n * 64 + ni * 8 + g;
                    const unsigned b0 = __float_as_uint(Bs[kk + tig][cb]);
                    const unsigned b1 = __float_as_uint(Bs[kk + tig + 4][cb]);
                    mma_tf32(acc[0][ni], afrag[0], b0, b1);
                    mma_tf32(acc[1][ni], afrag[1], b0, b1);
                }
            }
        }
        __syncthreads();
        if (has_next) { storeA(); storeB(); __syncthreads(); }
    }

    if (BW == 32 && warp_n != 0) return;

    #pragma unroll
    for (int mi = 0; mi < 2; mi++) {
        const int row = warp_m * 32 + mi * 16 + g;
        #pragma unroll
        for (int ni = 0; ni < NI; ni++) {
            const int col = warp_n * 64 + ni * 8 + 2 * tig;
            if (col >= BW) continue;
            const float bb0 = bias[col];
            const float bb1 = bias[col + 1];
            const int mg0 = m0 + row;
            const int mg1 = m0 + row + 8;
            if (packed) {
                const int hidx = ((col >> 2) << 3) + (col & 3) + voff;
                if (mg0 < n) {
                    __half2 h = __floats2half2_rn(acc[mi][ni][0] + bb0,
                                                  acc[mi][ni][1] + bb1);
                    *(__half2*)&g_kvh[(size_t)mg0 * 256 + hidx] = h;
                }
                if (mg1 < n) {
                    __half2 h = __floats2half2_rn(acc[mi][ni][2] + bb0,
                                                  acc[mi][ni][3] + bb1);
                    *(__half2*)&g_kvh[(size_t)mg1 * 256 + hidx] = h;
                }
            } else {
                if (mg0 < n) {
                    float2 o; o.x = acc[mi][ni][0] + bb0; o.y = acc[mi][ni][1] + bb1;
                    *(float2*)&outp[(size_t)mg0 * BW + col] = o;
                }
                if (mg1 < n) {
                    float2 o; o.x = acc[mi][ni][2] + bb0; o.y = acc[mi][ni][3] + bb1;
                    *(float2*)&outp[(size_t)mg1 * BW + col] = o;
                }
            }
        }
    }
}

// ================= CSR build ===============================================
__global__ void count_deg(const int* __restrict__ ei, int nE) {
    const int e = blockIdx.x * blockDim.x + threadIdx.x;
    if (e == 0) g_work = 0;   // fold work-cursor reset into side chain
    if (e < nE) atomicAdd(&g_deg[ei[nE + e]], 1);
}

#define SCAN_B 1024
__global__ void scan1(int n) {
    __shared__ int sh[SCAN_B];
    const int tid = threadIdx.x;
    const int i = blockIdx.x * SCAN_B + tid;
    const int v = (i < n) ? g_deg[i] : 0;
    sh[tid] = v;
    __syncthreads();
    #pragma unroll
    for (int off = 1; off < SCAN_B; off <<= 1) {
        int u = (tid >= off) ? sh[tid - off] : 0;
        __syncthreads();
        sh[tid] += u;
        __syncthreads();
    }
    if (i < n) g_off[i] = sh[tid] - v;   // exclusive
    if (tid == SCAN_B - 1) g_bsums[blockIdx.x] = sh[tid];
}

__global__ void scan2(int nb) {
    __shared__ int sh[64];
    const int tid = threadIdx.x;
    const int v = (tid < nb) ? g_bsums[tid] : 0;
    sh[tid] = v;
    __syncthreads();
    #pragma unroll
    for (int off = 1; off < 64; off <<= 1) {
        int u = (tid >= off) ? sh[tid - off] : 0;
        __syncthreads();
        sh[tid] += u;
        __syncthreads();
    }
    if (tid < nb) g_bsums[tid] = sh[tid] - v;  // exclusive
}

__global__ void scan3(int n) {
    const int i = blockIdx.x * SCAN_B + threadIdx.x;
    if (i < n && blockIdx.x > 0) g_off[i] += g_bsums[blockIdx.x];
}

// bump g_off[dst] directly: after this kernel g_off[dst] = inclusive end.
__global__ void scatter_csr(const int* __restrict__ ei,
                            const float* __restrict__ ew, int nE) {
    const int e = blockIdx.x * blockDim.x + threadIdx.x;
    if (e >= nE) return;
    const int src = ei[e];
    const int dst = ei[nE + e];
    const int pos = atomicAdd(&g_off[dst], 1);
    int2 sw;
    sw.x = src;
    sw.y = __float_as_int(ew[e]);
    g_csr[pos] = sw;
}

// ============ Fused node pass: persistent work-stealing warps ==============
// smem Wmlp stored as half2 (scale,shift) pairs: 17 kB -> 8 blocks/SM.
// beg(nn) = g_off[nn-1] (CSR contiguous) -> no g_deg read.
__global__ void __launch_bounds__(256) node_kernel(
    const float* __restrict__ x,
    const float* __restrict__ We, const float* __restrict__ be,
    const float* __restrict__ Wmlp, const float* __restrict__ bmlp,
    float* __restrict__ out, int n)
{
    __shared__ __half2 w_sh2[32 * 128];   // (Wmlp[d][c], Wmlp[d][c+128])
    __shared__ float bm_sh[256];
    for (int i = threadIdx.x; i < 32 * 128; i += 256) {
        const int d = i >> 7;
        const int c = i & 127;
        w_sh2[i] = __floats2half2_rn(Wmlp[d * 256 + c], Wmlp[d * 256 + 128 + c]);
    }
    if (threadIdx.x < 256) bm_sh[threadIdx.x] = bmlp[threadIdx.x];
    __syncthreads();

    const int lane = threadIdx.x & 31;

    const float4 We4 = ((const float4*)We)[lane];
    const float4 be4 = ((const float4*)be)[lane];
    const uint4* kvp = (const uint4*)g_kvh;

    // grab first node + its metadata
    int cur = 0;
    if (lane == 0) cur = atomicAdd(&g_work, 1);
    cur = __shfl_sync(0xffffffffu, cur, 0);

    int curBeg = 0, curEnd = 0;
    float4 curQ = make_float4(0.f, 0.f, 0.f, 0.f);
    if (cur < n) {
        curBeg = (cur == 0) ? 0 : g_off[cur - 1];
        curEnd = g_off[cur];
        curQ = ((const float4*)g_q)[cur * 32 + lane];
    }

    while (cur < n) {
        // prefetch next node id + metadata (hidden under this node's work)
        int nxt = 0;
        if (lane == 0) nxt = atomicAdd(&g_work, 1);
        nxt = __shfl_sync(0xffffffffu, nxt, 0);
        int nxtBeg = 0, nxtEnd = 0;
        float4 nxtQ = make_float4(0.f, 0.f, 0.f, 0.f);
        if (nxt < n) {
            nxtBeg = (nxt == 0) ? 0 : g_off[nxt - 1];
            nxtEnd = g_off[nxt];
            nxtQ = ((const float4*)g_q)[nxt * 32 + lane];
        }

        const int nn = cur;
        const float4 q4 = curQ;

        // per-head dots q.We and q.be (replicated across the head's 8 lanes)
        float qWe = q4.x * We4.x + q4.y * We4.y + q4.z * We4.z + q4.w * We4.w;
        float qbe = q4.x * be4.x + q4.y * be4.y + q4.z * be4.z + q4.w * be4.w;
        #pragma unroll
        for (int m = 1; m <= 4; m <<= 1) {
            qWe += __shfl_xor_sync(0xffffffffu, qWe, m);
            qbe += __shfl_xor_sync(0xffffffffu, qbe, m);
        }

        const int beg = curBeg;
        const int end = curEnd;
        const int cnt = end - beg;

        float4 macc = make_float4(0.f, 0.f, 0.f, 0.f);
        float dsum = 0.f;   // Sum p
        float wsum = 0.f;   // Sum wt*p

        int j = beg;
        const int lim = beg + (cnt & ~3);
        for (; j < lim; j += 4) {
            int2 sw[4];
            #pragma unroll
            for (int i = 0; i < 4; i++) sw[i] = g_csr[j + i];
            uint4 raw[4];
            #pragma unroll
            for (int i = 0; i < 4; i++) raw[i] = kvp[sw[i].x * 32 + lane];

            float s[4];
            #pragma unroll
            for (int i = 0; i < 4; i++) {
                const float2 k01 = __half22float2(*(const __half2*)&raw[i].x);
                const float2 k23 = __half22float2(*(const __half2*)&raw[i].y);
                s[i] = q4.x * k01.x + q4.y * k01.y + q4.z * k23.x + q4.w * k23.y;
            }
            #pragma unroll
            for (int i = 0; i < 4; i++) {
                s[i] += __shfl_xor_sync(0xffffffffu, s[i], 1);
                s[i] += __shfl_xor_sync(0xffffffffu, s[i], 2);
                s[i] += __shfl_xor_sync(0xffffffffu, s[i], 4);
            }
            #pragma unroll
            for (int i = 0; i < 4; i++) {
                const float2 v01 = __half22float2(*(const __half2*)&raw[i].z);
                const float2 v23 = __half22float2(*(const __half2*)&raw[i].w);
                const float wt = __int_as_float(sw[i].y);
                const float alpha = s[i] + fmaf(wt, qWe, qbe);
                const float p = __expf(alpha * 0.17677669529663689f);  // 1/sqrt(32)
                dsum += p;
                wsum = fmaf(wt, p, wsum);
                macc.x = fmaf(v01.x, p, macc.x);
                macc.y = fmaf(v01.y, p, macc.y);
                macc.z = fmaf(v23.x, p, macc.z);
                macc.w = fmaf(v23.y, p, macc.w);
            }
        }
        for (; j < end; j++) {
            const int2 sw = g_csr[j];
            const uint4 raw = kvp[sw.x * 32 + lane];
            const float2 k01 = __half22float2(*(const __half2*)&raw.x);
            const float2 k23 = __half22float2(*(const __half2*)&raw.y);
            const float2 v01 = __half22float2(*(const __half2*)&raw.z);
            const float2 v23 = __half22float2(*(const __half2*)&raw.w);
            float s = q4.x * k01.x + q4.y * k01.y + q4.z * k23.x + q4.w * k23.y;
            s += __shfl_xor_sync(0xffffffffu, s, 1);
            s += __shfl_xor_sync(0xffffffffu, s, 2);
            s += __shfl_xor_sync(0xffffffffu, s, 4);
            const float wt = __int_as_float(sw.y);
            const float alpha = s + fmaf(wt, qWe, qbe);
            const float p = __expf(alpha * 0.17677669529663689f);
            dsum += p;
            wsum = fmaf(wt, p, wsum);
            macc.x = fmaf(v01.x, p, macc.x);
            macc.y = fmaf(v01.y, p, macc.y);
            macc.z = fmaf(v23.x, p, macc.z);
            macc.w = fmaf(v23.y, p, macc.w);
        }

        // z = (Sum v p + We*Sum(wt p) + be*Sum p) / (Sum p + eps), per head
        const float inv = 1.f / (dsum + 1e-16f);
        float4 z4;
        z4.x = (macc.x + We4.x * wsum + be4.x * dsum) * inv;
        z4.y = (macc.y + We4.y * wsum + be4.y * dsum) * inv;
        z4.z = (macc.z + We4.z * wsum + be4.z * dsum) * inv;
        z4.w = (macc.w + We4.w * wsum + be4.w * dsum) * inv;

        #pragma unroll
        for (int m = 8; m <= 16; m <<= 1) {
            z4.x += __shfl_xor_sync(0xffffffffu, z4.x, m);
            z4.y += __shfl_xor_sync(0xffffffffu, z4.y, m);
            z4.z += __shfl_xor_sync(0xffffffffu, z4.z, m);
            z4.w += __shfl_xor_sync(0xffffffffu, z4.w, m);
        }

        const int u = lane & 7;
        const float4 sk = ((const float4*)g_skip)[nn * 8 + u];
        float4 y4;
        y4.x = tanhf(z4.x * 0.25f + sk.x);
        y4.y = tanhf(z4.y * 0.25f + sk.y);
        y4.z = tanhf(z4.z * 0.25f + sk.z);
        y4.w = tanhf(z4.w * 0.25f + sk.w);

        float accS[4] = {0.f, 0.f, 0.f, 0.f};
        float accH[4] = {0.f, 0.f, 0.f, 0.f};
        #pragma unroll
        for (int uu = 0; uu < 8; uu++) {
            const float b0 = __shfl_sync(0xffffffffu, y4.x, uu);
            const float b1 = __shfl_sync(0xffffffffu, y4.y, uu);
            const float b2 = __shfl_sync(0xffffffffu, y4.z, uu);
            const float b3 = __shfl_sync(0xffffffffu, y4.w, uu);
            const int d0 = 4 * uu;
            #pragma unroll
            for (int k = 0; k < 4; k++) {
                const int c = lane + 32 * k;
                float2 w0 = __half22float2(w_sh2[(d0 + 0) * 128 + c]);
                float2 w1 = __half22float2(w_sh2[(d0 + 1) * 128 + c]);
                float2 w2 = __half22float2(w_sh2[(d0 + 2) * 128 + c]);
                float2 w3 = __half22float2(w_sh2[(d0 + 3) * 128 + c]);
                accS[k] = fmaf(b0, w0.x, accS[k]);
                accH[k] = fmaf(b0, w0.y, accH[k]);
                accS[k] = fmaf(b1, w1.x, accS[k]);
                accH[k] = fmaf(b1, w1.y, accH[k]);
                accS[k] = fmaf(b2, w2.x, accS[k]);
                accH[k] = fmaf(b2, w2.y, accH[k]);
                accS[k] = fmaf(b3, w3.x, accS[k]);
                accH[k] = fmaf(b3, w3.y, accH[k]);
            }
        }
        #pragma unroll
        for (int k = 0; k < 4; k++) {
            const int c = lane + 32 * k;
            const float sc = tanhf(accS[k] + bm_sh[c]);
            const float sh = tanhf(accH[k] + bm_sh[128 + c]);
            out[(size_t)nn * 128 + c] = fmaf(x[(size_t)nn * 128 + c], sc, sh);
        }

        cur = nxt; curBeg = nxtBeg; curEnd = nxtEnd; curQ = nxtQ;
    }
}

// ================= launch ==================================================
extern "C" void kernel_launch(void* const* d_in, const int* in_sizes, int n_in,
                              void* d_out, int out_size)
{
    const float* x     = (const float*)d_in[0];
    const float* t     = (const float*)d_in[1];
    const int*   ei    = (const int*)  d_in[2];
    const float* ew    = (const float*)d_in[3];
    const float* Wq    = (const float*)d_in[4];
    const float* bq    = (const float*)d_in[5];
    const float* Wk    = (const float*)d_in[6];
    const float* bk    = (const float*)d_in[7];
    const float* Wv    = (const float*)d_in[8];
    const float* bv    = (const float*)d_in[9];
    const float* We    = (const float*)d_in[10];
    const float* be    = (const float*)d_in[11];
    const float* Wskip = (const float*)d_in[12];
    const float* bskip = (const float*)d_in[13];
    const float* Wmlp  = (const float*)d_in[14];
    const float* bmlp  = (const float*)d_in[15];
    float* out = (float*)d_out;

    const int n  = in_sizes[0] / 128;
    const int nE = in_sizes[3];

    // one-time side stream + fork/join events (same work every call)
    static cudaStream_t sB = nullptr;
    static cudaEvent_t evFork = nullptr, evJoin = nullptr;
    if (sB == nullptr) {
        cudaStreamCreateWithFlags(&sB, cudaStreamNonBlocking);
        cudaEventCreateWithFlags(&evFork, cudaEventDisableTiming);
        cudaEventCreateWithFlags(&evJoin, cudaEventDisableTiming);
    }

    void *degPtr = nullptr;
    cudaGetSymbolAddress(&degPtr, g_deg);

    // ---- fork: skip GEMM first, then CSR build on side stream ------------
    cudaEventRecord(evFork, 0);
    cudaStreamWaitEvent(sB, evFork, 0);

    const int gm = (n + BM - 1) / BM;
    gemm_tf32<32><<<dim3(gm, 1), 256, 0, sB>>>(x, t, Wq, bq, Wk, bk, Wv, bv,
                                               Wskip, bskip, n);
    cudaMemsetAsync(degPtr, 0, (size_t)n * sizeof(int), sB);
    count_deg<<<(nE + 255) / 256, 256, 0, sB>>>(ei, nE);
    const int nb = (n + SCAN_B - 1) / SCAN_B;
    scan1<<<nb, SCAN_B, 0, sB>>>(n);
    scan2<<<1, 64, 0, sB>>>(nb);
    scan3<<<nb, SCAN_B, 0, sB>>>(n);
    scatter_csr<<<(nE + 255) / 256, 256, 0, sB>>>(ei, ew, nE);
    cudaEventRecord(evJoin, sB);

    // main stream: q,k,v (BW=128, 3 slices)
    gemm_tf32<128><<<dim3(gm, 3), 256>>>(x, t, Wq, bq, Wk, bk, Wv, bv,
                                         Wskip, bskip, n);

    // ---- join, then fused attention + epilogue (persistent grid) ---------
    cudaStreamWaitEvent(0, evJoin, 0);
    node_kernel<<<148 * 8, 256>>>(x, We, be, Wmlp, bmlp, out, n);
}

// round 17
// speedup vs baseline: 1.3398x; 1.1283x over previous
#include <cuda_runtime.h>
#include <cuda_fp16.h>
#include <math.h>

#define N_NODES 50000
#define N_EDGES 800000

// ---------------- scratch (no cudaMalloc allowed) ----------------
__device__ float   g_q[N_NODES * 128];
__device__ __half  g_kvh[N_NODES * 256];  // packed per row: [k(4)|v(4)] x 32 lanes
__device__ float   g_skip[N_NODES * 32];
__device__ int     g_deg[N_NODES];
__device__ int     g_off[N_NODES];      // exclusive prefix; after scatter = inclusive end
__device__ int2    g_csr[N_EDGES];      // (src, bitcast(weight)) grouped by dst
__device__ int     g_bsums[64];
__device__ int     g_work;              // work-stealing cursor for node pass
// fp16 weights, k-pair packed: per slice, [k2][n] half2 = (W[2k2][n], W[2k2+1][n])
// slice offsets (half2): q=0, k=16384, v=32768, skip=49152 (32 cols)
__device__ __half2 g_wh[128 * 416];

// ================= weight pre-pack (fp32 -> fp16 k-pair) ===================
__global__ void conv_w(const float* __restrict__ Wq, const float* __restrict__ Wk,
                       const float* __restrict__ Wv, const float* __restrict__ Ws) {
    for (int idx = blockIdx.x * blockDim.x + threadIdx.x; idx < 128 * 416;
         idx += gridDim.x * blockDim.x) {
        const int k2 = idx / 416;
        const int j = idx - k2 * 416;
        float a, b;
        int dst;
        if (j < 128)      { a = Wq[(2 * k2) * 128 + j];       b = Wq[(2 * k2 + 1) * 128 + j];       dst = k2 * 128 + j; }
        else if (j < 256) { a = Wk[(2 * k2) * 128 + j - 128]; b = Wk[(2 * k2 + 1) * 128 + j - 128]; dst = 16384 + k2 * 128 + (j - 128); }
        else if (j < 384) { a = Wv[(2 * k2) * 128 + j - 256]; b = Wv[(2 * k2 + 1) * 128 + j - 256]; dst = 32768 + k2 * 128 + (j - 256); }
        else              { a = Ws[(2 * k2) * 32 + j - 384];  b = Ws[(2 * k2 + 1) * 32 + j - 384];  dst = 49152 + k2 * 32 + (j - 384); }
        g_wh[dst] = __floats2half2_rn(a, b);
    }
}

// ================= fp16 tensor-core GEMM (same tiling as proven tf32) ======
#define BM 128
#define BN 128
#define BK 32
#define AS_STRIDE 40    // halves per A row: banks 20g+tig -> conflict-free
#define BS_STRIDE 136   // half2 per B k2-row: banks 8tig+g -> conflict-free

__device__ __forceinline__ void mma_f16(float* c, const unsigned* a,
                                        unsigned b0, unsigned b1) {
    asm volatile(
        "mma.sync.aligned.m16n8k16.row.col.f32.f16.f16.f32 "
        "{%0,%1,%2,%3}, {%4,%5,%6,%7}, {%8,%9}, {%0,%1,%2,%3};\n"
        : "+f"(c[0]), "+f"(c[1]), "+f"(c[2]), "+f"(c[3])
        : "r"(a[0]), "r"(a[1]), "r"(a[2]), "r"(a[3]), "r"(b0), "r"(b1));
}

__device__ __forceinline__ unsigned pack_h2(float a, float b) {
    __half2 h = __floats2half2_rn(a, b);
    return *(unsigned*)&h;
}

// BW=128: slices 0..2 (q, kv-packed). BW=32: skip slice, only warp_n==0, NI=4.
template<int BW>
__global__ void __launch_bounds__(256, 2) gemm_f16(
    const float* __restrict__ x, const float* __restrict__ t,
    const float* __restrict__ bq, const float* __restrict__ bk,
    const float* __restrict__ bv, const float* __restrict__ bs,
    int n)
{
    __shared__ __half  As[BM * AS_STRIDE];      // 10.2 kB
    __shared__ __half2 Bsm[(BK / 2) * BS_STRIDE]; // 8.7 kB

    const int m0 = blockIdx.x * BM;
    const int slice = blockIdx.y;

    const float* bias; float* outp = nullptr;
    int woff, voff = 0; bool packed = false;
    if (BW == 32)        { bias = bs; outp = g_skip; woff = 49152; }
    else if (slice == 0) { bias = bq; outp = g_q;    woff = 0; }
    else if (slice == 1) { bias = bk; packed = true; voff = 0; woff = 16384; }
    else                 { bias = bv; packed = true; voff = 4; woff = 32768; }

    const int tid = threadIdx.x;
    const int lane = tid & 31;
    const int wid = tid >> 5;
    const int warp_m = wid & 3;
    const int warp_n = wid >> 2;
    const int g = lane >> 2;
    const int tig = lane & 3;

    constexpr int NI = (BW == 128) ? 8 : 4;
    float acc[2][NI][4];
    #pragma unroll
    for (int mi = 0; mi < 2; mi++)
        #pragma unroll
        for (int ni = 0; ni < NI; ni++)
            #pragma unroll
            for (int c = 0; c < 4; c++) acc[mi][ni][c] = 0.f;

    // ---- staging registers ----
    float4 ar[4];           // A: 16 floats of one row-half
    uint4  bstage[2];       // B: pre-packed half2 from g_wh

    const int a_row = tid >> 1;
    const int a_h0  = (tid & 1) * 16;   // half offset within row

    auto loadA = [&](int k0) {
        const int mg = m0 + a_row;
        const int xbase = (k0 < 128 ? k0 : k0 - 128) + (tid & 1) * 16;
        float mult = 0.f;
        if (mg < n) mult = (k0 < 128) ? 1.f : t[mg];
        const float4* xr = (const float4*)&x[(size_t)(mg < n ? mg : 0) * 128 + xbase];
        #pragma unroll
        for (int i = 0; i < 4; i++) {
            float4 v = xr[i];
            ar[i].x = v.x * mult; ar[i].y = v.y * mult;
            ar[i].z = v.z * mult; ar[i].w = v.w * mult;
        }
    };
    auto storeA = [&]() {
        uint4 u0, u1;
        u0.x = pack_h2(ar[0].x, ar[0].y); u0.y = pack_h2(ar[0].z, ar[0].w);
        u0.z = pack_h2(ar[1].x, ar[1].y); u0.w = pack_h2(ar[1].z, ar[1].w);
        u1.x = pack_h2(ar[2].x, ar[2].y); u1.y = pack_h2(ar[2].z, ar[2].w);
        u1.z = pack_h2(ar[3].x, ar[3].y); u1.w = pack_h2(ar[3].z, ar[3].w);
        __half* dst = &As[a_row * AS_STRIDE + a_h0];
        *(uint4*)dst = u0;
        *(uint4*)(dst + 8) = u1;
    };
    auto loadB = [&](int k0) {
        const int k02 = k0 >> 1;
        if (BW == 128) {
            #pragma unroll
            for (int c = 0; c < 2; c++) {
                const int id = c * 256 + tid;       // 512 uint4 per stage
                const int row = id >> 5;            // k2 row 0..15
                const int c4 = id & 31;             // 4-half2 chunk
                bstage[c] = *(const uint4*)&g_wh[woff + (k02 + row) * 128 + c4 * 4];
            }
        } else {
            if (tid < 128) {
                const int row = tid >> 3;
                const int c4 = tid & 7;
                bstage[0] = *(const uint4*)&g_wh[woff + (k02 + row) * 32 + c4 * 4];
            }
        }
    };
    auto storeB = [&]() {
        if (BW == 128) {
            #pragma unroll
            for (int c = 0; c < 2; c++) {
                const int id = c * 256 + tid;
                const int row = id >> 5;
                const int c4 = id & 31;
                *(uint4*)&Bsm[row * BS_STRIDE + c4 * 4] = bstage[c];
            }
        } else {
            if (tid < 128) {
                const int row = tid >> 3;
                const int c4 = tid & 7;
                *(uint4*)&Bsm[row * BS_STRIDE + c4 * 4] = bstage[0];
            }
        }
    };

    loadA(0); loadB(0);
    storeA(); storeB();
    __syncthreads();

    for (int k0 = 0; k0 < 256; k0 += BK) {
        const bool has_next = (k0 + BK) < 256;
        if (has_next) { loadA(k0 + BK); loadB(k0 + BK); }

        if (BW == 128 || warp_n == 0) {
            #pragma unroll
            for (int kk2 = 0; kk2 < 16; kk2 += 8) {   // two k=16 steps
                const int kk = kk2 * 2;
                unsigned afrag[2][4];
                #pragma unroll
                for (int mi = 0; mi < 2; mi++) {
                    const int r0 = warp_m * 32 + mi * 16 + g;
                    const __half* a0 = &As[r0 * AS_STRIDE + kk + 2 * tig];
                    const __half* a1 = &As[(r0 + 8) * AS_STRIDE + kk + 2 * tig];
                    afrag[mi][0] = *(const unsigned*)a0;
                    afrag[mi][1] = *(const unsigned*)a1;
                    afrag[mi][2] = *(const unsigned*)(a0 + 8);
                    afrag[mi][3] = *(const unsigned*)(a1 + 8);
                }
                #pragma unroll
                for (int ni = 0; ni < NI; ni++) {
                    const int cb = warp_n * 64 + ni * 8 + g;
                    const unsigned b0 = *(const unsigned*)&Bsm[(kk2 + tig) * BS_STRIDE + cb];
                    const unsigned b1 = *(const unsigned*)&Bsm[(kk2 + tig + 4) * BS_STRIDE + cb];
                    mma_f16(acc[0][ni], afrag[0], b0, b1);
                    mma_f16(acc[1][ni], afrag[1], b0, b1);
                }
            }
        }
        __syncthreads();
        if (has_next) { storeA(); storeB(); __syncthreads(); }
    }

    if (BW == 32 && warp_n != 0) return;

    #pragma unroll
    for (int mi = 0; mi < 2; mi++) {
        const int row = warp_m * 32 + mi * 16 + g;
        #pragma unroll
        for (int ni = 0; ni < NI; ni++) {
            const int col = warp_n * 64 + ni * 8 + 2 * tig;
            if (col >= BW) continue;
            const float bb0 = bias[col];
            const float bb1 = bias[col + 1];
            const int mg0 = m0 + row;
            const int mg1 = m0 + row + 8;
            if (packed) {
                const int hidx = ((col >> 2) << 3) + (col & 3) + voff;
                if (mg0 < n) {
                    __half2 h = __floats2half2_rn(acc[mi][ni][0] + bb0,
                                                  acc[mi][ni][1] + bb1);
                    *(__half2*)&g_kvh[(size_t)mg0 * 256 + hidx] = h;
                }
                if (mg1 < n) {
                    __half2 h = __floats2half2_rn(acc[mi][ni][2] + bb0,
                                                  acc[mi][ni][3] + bb1);
                    *(__half2*)&g_kvh[(size_t)mg1 * 256 + hidx] = h;
                }
            } else {
                if (mg0 < n) {
                    float2 o; o.x = acc[mi][ni][0] + bb0; o.y = acc[mi][ni][1] + bb1;
                    *(float2*)&outp[(size_t)mg0 * BW + col] = o;
                }
                if (mg1 < n) {
                    float2 o; o.x = acc[mi][ni][2] + bb0; o.y = acc[mi][ni][3] + bb1;
                    *(float2*)&outp[(size_t)mg1 * BW + col] = o;
                }
            }
        }
    }
}

// ================= CSR build ===============================================
__global__ void count_deg(const int* __restrict__ ei, int nE) {
    const int e = blockIdx.x * blockDim.x + threadIdx.x;
    if (e == 0) g_work = 0;   // fold work-cursor reset into side chain
    if (e < nE) atomicAdd(&g_deg[ei[nE + e]], 1);
}

#define SCAN_B 1024
__global__ void scan1(int n) {
    __shared__ int sh[SCAN_B];
    const int tid = threadIdx.x;
    const int i = blockIdx.x * SCAN_B + tid;
    const int v = (i < n) ? g_deg[i] : 0;
    sh[tid] = v;
    __syncthreads();
    #pragma unroll
    for (int off = 1; off < SCAN_B; off <<= 1) {
        int u = (tid >= off) ? sh[tid - off] : 0;
        __syncthreads();
        sh[tid] += u;
        __syncthreads();
    }
    if (i < n) g_off[i] = sh[tid] - v;   // exclusive
    if (tid == SCAN_B - 1) g_bsums[blockIdx.x] = sh[tid];
}

__global__ void scan2(int nb) {
    __shared__ int sh[64];
    const int tid = threadIdx.x;
    const int v = (tid < nb) ? g_bsums[tid] : 0;
    sh[tid] = v;
    __syncthreads();
    #pragma unroll
    for (int off = 1; off < 64; off <<= 1) {
        int u = (tid >= off) ? sh[tid - off] : 0;
        __syncthreads();
        sh[tid] += u;
        __syncthreads();
    }
    if (tid < nb) g_bsums[tid] = sh[tid] - v;  // exclusive
}

__global__ void scan3(int n) {
    const int i = blockIdx.x * SCAN_B + threadIdx.x;
    if (i < n && blockIdx.x > 0) g_off[i] += g_bsums[blockIdx.x];
}

// bump g_off[dst] directly: after this kernel g_off[dst] = inclusive end.
__global__ void scatter_csr(const int* __restrict__ ei,
                            const float* __restrict__ ew, int nE) {
    const int e = blockIdx.x * blockDim.x + threadIdx.x;
    if (e >= nE) return;
    const int src = ei[e];
    const int dst = ei[nE + e];
    const int pos = atomicAdd(&g_off[dst], 1);
    int2 sw;
    sw.x = src;
    sw.y = __float_as_int(ew[e]);
    g_csr[pos] = sw;
}

// ============ Fused node pass: persistent work-stealing warps ==============
__global__ void __launch_bounds__(256) node_kernel(
    const float* __restrict__ x,
    const float* __restrict__ We, const float* __restrict__ be,
    const float* __restrict__ Wmlp, const float* __restrict__ bmlp,
    float* __restrict__ out, int n)
{
    __shared__ __half2 w_sh2[32 * 128];   // (Wmlp[d][c], Wmlp[d][c+128])
    __shared__ float bm_sh[256];
    for (int i = threadIdx.x; i < 32 * 128; i += 256) {
        const int d = i >> 7;
        const int c = i & 127;
        w_sh2[i] = __floats2half2_rn(Wmlp[d * 256 + c], Wmlp[d * 256 + 128 + c]);
    }
    if (threadIdx.x < 256) bm_sh[threadIdx.x] = bmlp[threadIdx.x];
    __syncthreads();

    const int lane = threadIdx.x & 31;

    const float4 We4 = ((const float4*)We)[lane];
    const float4 be4 = ((const float4*)be)[lane];
    const uint4* kvp = (const uint4*)g_kvh;

    int cur = 0;
    if (lane == 0) cur = atomicAdd(&g_work, 1);
    cur = __shfl_sync(0xffffffffu, cur, 0);

    int curBeg = 0, curEnd = 0;
    float4 curQ = make_float4(0.f, 0.f, 0.f, 0.f);
    if (cur < n) {
        curBeg = (cur == 0) ? 0 : g_off[cur - 1];
        curEnd = g_off[cur];
        curQ = ((const float4*)g_q)[cur * 32 + lane];
    }

    while (cur < n) {
        int nxt = 0;
        if (lane == 0) nxt = atomicAdd(&g_work, 1);
        nxt = __shfl_sync(0xffffffffu, nxt, 0);
        int nxtBeg = 0, nxtEnd = 0;
        float4 nxtQ = make_float4(0.f, 0.f, 0.f, 0.f);
        if (nxt < n) {
            nxtBeg = (nxt == 0) ? 0 : g_off[nxt - 1];
            nxtEnd = g_off[nxt];
            nxtQ = ((const float4*)g_q)[nxt * 32 + lane];
        }

        const int nn = cur;
        const float4 q4 = curQ;

        float qWe = q4.x * We4.x + q4.y * We4.y + q4.z * We4.z + q4.w * We4.w;
        float qbe = q4.x * be4.x + q4.y * be4.y + q4.z * be4.z + q4.w * be4.w;
        #pragma unroll
        for (int m = 1; m <= 4; m <<= 1) {
            qWe += __shfl_xor_sync(0xffffffffu, qWe, m);
            qbe += __shfl_xor_sync(0xffffffffu, qbe, m);
        }

        const int beg = curBeg;
        const int end = curEnd;
        const int cnt = end - beg;

        float4 macc = make_float4(0.f, 0.f, 0.f, 0.f);
        float dsum = 0.f;
        float wsum = 0.f;

        int j = beg;
        const int lim = beg + (cnt & ~3);
        for (; j < lim; j += 4) {
            int2 sw[4];
            #pragma unroll
            for (int i = 0; i < 4; i++) sw[i] = g_csr[j + i];
            uint4 raw[4];
            #pragma unroll
            for (int i = 0; i < 4; i++) raw[i] = kvp[sw[i].x * 32 + lane];

            float s[4];
            #pragma unroll
            for (int i = 0; i < 4; i++) {
                const float2 k01 = __half22float2(*(const __half2*)&raw[i].x);
                const float2 k23 = __half22float2(*(const __half2*)&raw[i].y);
                s[i] = q4.x * k01.x + q4.y * k01.y + q4.z * k23.x + q4.w * k23.y;
            }
            #pragma unroll
            for (int i = 0; i < 4; i++) {
                s[i] += __shfl_xor_sync(0xffffffffu, s[i], 1);
                s[i] += __shfl_xor_sync(0xffffffffu, s[i], 2);
                s[i] += __shfl_xor_sync(0xffffffffu, s[i], 4);
            }
            #pragma unroll
            for (int i = 0; i < 4; i++) {
                const float2 v01 = __half22float2(*(const __half2*)&raw[i].z);
                const float2 v23 = __half22float2(*(const __half2*)&raw[i].w);
                const float wt = __int_as_float(sw[i].y);
                const float alpha = s[i] + fmaf(wt, qWe, qbe);
                const float p = __expf(alpha * 0.17677669529663689f);  // 1/sqrt(32)
                dsum += p;
                wsum = fmaf(wt, p, wsum);
                macc.x = fmaf(v01.x, p, macc.x);
                macc.y = fmaf(v01.y, p, macc.y);
                macc.z = fmaf(v23.x, p, macc.z);
                macc.w = fmaf(v23.y, p, macc.w);
            }
        }
        for (; j < end; j++) {
            const int2 sw = g_csr[j];
            const uint4 raw = kvp[sw.x * 32 + lane];
            const float2 k01 = __half22float2(*(const __half2*)&raw.x);
            const float2 k23 = __half22float2(*(const __half2*)&raw.y);
            const float2 v01 = __half22float2(*(const __half2*)&raw.z);
            const float2 v23 = __half22float2(*(const __half2*)&raw.w);
            float s = q4.x * k01.x + q4.y * k01.y + q4.z * k23.x + q4.w * k23.y;
            s += __shfl_xor_sync(0xffffffffu, s, 1);
            s += __shfl_xor_sync(0xffffffffu, s, 2);
            s += __shfl_xor_sync(0xffffffffu, s, 4);
            const float wt = __int_as_float(sw.y);
            const float alpha = s + fmaf(wt, qWe, qbe);
            const float p = __expf(alpha * 0.17677669529663689f);
            dsum += p;
            wsum = fmaf(wt, p, wsum);
            macc.x = fmaf(v01.x, p, macc.x);
            macc.y = fmaf(v01.y, p, macc.y);
            macc.z = fmaf(v23.x, p, macc.z);
            macc.w = fmaf(v23.y, p, macc.w);
        }

        const float inv = 1.f / (dsum + 1e-16f);
        float4 z4;
        z4.x = (macc.x + We4.x * wsum + be4.x * dsum) * inv;
        z4.y = (macc.y + We4.y * wsum + be4.y * dsum) * inv;
        z4.z = (macc.z + We4.z * wsum + be4.z * dsum) * inv;
        z4.w = (macc.w + We4.w * wsum + be4.w * dsum) * inv;

        #pragma unroll
        for (int m = 8; m <= 16; m <<= 1) {
            z4.x += __shfl_xor_sync(0xffffffffu, z4.x, m);
            z4.y += __shfl_xor_sync(0xffffffffu, z4.y, m);
            z4.z += __shfl_xor_sync(0xffffffffu, z4.z, m);
            z4.w += __shfl_xor_sync(0xffffffffu, z4.w, m);
        }

        const int u = lane & 7;
        const float4 sk = ((const float4*)g_skip)[nn * 8 + u];
        float4 y4;
        y4.x = tanhf(z4.x * 0.25f + sk.x);
        y4.y = tanhf(z4.y * 0.25f + sk.y);
        y4.z = tanhf(z4.z * 0.25f + sk.z);
        y4.w = tanhf(z4.w * 0.25f + sk.w);

        float accS[4] = {0.f, 0.f, 0.f, 0.f};
        float accH[4] = {0.f, 0.f, 0.f, 0.f};
        #pragma unroll
        for (int uu = 0; uu < 8; uu++) {
            const float b0 = __shfl_sync(0xffffffffu, y4.x, uu);
            const float b1 = __shfl_sync(0xffffffffu, y4.y, uu);
            const float b2 = __shfl_sync(0xffffffffu, y4.z, uu);
            const float b3 = __shfl_sync(0xffffffffu, y4.w, uu);
            const int d0 = 4 * uu;
            #pragma unroll
            for (int k = 0; k < 4; k++) {
                const int c = lane + 32 * k;
                float2 w0 = __half22float2(w_sh2[(d0 + 0) * 128 + c]);
                float2 w1 = __half22float2(w_sh2[(d0 + 1) * 128 + c]);
                float2 w2 = __half22float2(w_sh2[(d0 + 2) * 128 + c]);
                float2 w3 = __half22float2(w_sh2[(d0 + 3) * 128 + c]);
                accS[k] = fmaf(b0, w0.x, accS[k]);
                accH[k] = fmaf(b0, w0.y, accH[k]);
                accS[k] = fmaf(b1, w1.x, accS[k]);
                accH[k] = fmaf(b1, w1.y, accH[k]);
                accS[k] = fmaf(b2, w2.x, accS[k]);
                accH[k] = fmaf(b2, w2.y, accH[k]);
                accS[k] = fmaf(b3, w3.x, accS[k]);
                accH[k] = fmaf(b3, w3.y, accH[k]);
            }
        }
        #pragma unroll
        for (int k = 0; k < 4; k++) {
            const int c = lane + 32 * k;
            const float sc = tanhf(accS[k] + bm_sh[c]);
            const float sh = tanhf(accH[k] + bm_sh[128 + c]);
            out[(size_t)nn * 128 + c] = fmaf(x[(size_t)nn * 128 + c], sc, sh);
        }

        cur = nxt; curBeg = nxtBeg; curEnd = nxtEnd; curQ = nxtQ;
    }
}

// ================= launch ==================================================
extern "C" void kernel_launch(void* const* d_in, const int* in_sizes, int n_in,
                              void* d_out, int out_size)
{
    const float* x     = (const float*)d_in[0];
    const float* t     = (const float*)d_in[1];
    const int*   ei    = (const int*)  d_in[2];
    const float* ew    = (const float*)d_in[3];
    const float* Wq    = (const float*)d_in[4];
    const float* bq    = (const float*)d_in[5];
    const float* Wk    = (const float*)d_in[6];
    const float* bk    = (const float*)d_in[7];
    const float* Wv    = (const float*)d_in[8];
    const float* bv    = (const float*)d_in[9];
    const float* We    = (const float*)d_in[10];
    const float* be    = (const float*)d_in[11];
    const float* Wskip = (const float*)d_in[12];
    const float* bskip = (const float*)d_in[13];
    const float* Wmlp  = (const float*)d_in[14];
    const float* bmlp  = (const float*)d_in[15];
    float* out = (float*)d_out;

    const int n  = in_sizes[0] / 128;
    const int nE = in_sizes[3];

    static cudaStream_t sB = nullptr;
    static cudaEvent_t evFork = nullptr, evW = nullptr, evJoin = nullptr;
    if (sB == nullptr) {
        cudaStreamCreateWithFlags(&sB, cudaStreamNonBlocking);
        cudaEventCreateWithFlags(&evFork, cudaEventDisableTiming);
        cudaEventCreateWithFlags(&evW, cudaEventDisableTiming);
        cudaEventCreateWithFlags(&evJoin, cudaEventDisableTiming);
    }

    void *degPtr = nullptr;
    cudaGetSymbolAddress(&degPtr, g_deg);

    const int gm = (n + BM - 1) / BM;

    // ---- main: pack weights (tiny), record evW ---------------------------
    conv_w<<<52, 1024>>>(Wq, Wk, Wv, Wskip);
    cudaEventRecord(evW, 0);

    // ---- fork side: CSR front half (W-independent), then skip GEMM, rest -
    cudaEventRecord(evFork, 0);
    cudaStreamWaitEvent(sB, evFork, 0);

    cudaMemsetAsync(degPtr, 0, (size_t)n * sizeof(int), sB);
    count_deg<<<(nE + 255) / 256, 256, 0, sB>>>(ei, nE);
    cudaStreamWaitEvent(sB, evW, 0);
    gemm_f16<32><<<dim3(gm, 1), 256, 0, sB>>>(x, t, bq, bk, bv, bskip, n);
    const int nb = (n + SCAN_B - 1) / SCAN_B;
    scan1<<<nb, SCAN_B, 0, sB>>>(n);
    scan2<<<1, 64, 0, sB>>>(nb);
    scan3<<<nb, SCAN_B, 0, sB>>>(n);
    scatter_csr<<<(nE + 255) / 256, 256, 0, sB>>>(ei, ew, nE);
    cudaEventRecord(evJoin, sB);

    // ---- main: q,k,v GEMM (fp16 MMA) -------------------------------------
    gemm_f16<128><<<dim3(gm, 3), 256>>>(x, t, bq, bk, bv, bskip, n);

    // ---- join, then fused attention + epilogue (persistent grid) ---------
    cudaStreamWaitEvent(0, evJoin, 0);
    node_kernel<<<148 * 8, 256>>>(x, We, be, Wmlp, bmlp, out, n);
}